// round 1
// baseline (speedup 1.0000x reference)
#include <cuda_runtime.h>
#include <math.h>

#define Bsz 16
#define Tt 64
#define NV 49
#define NP 50
#define Hd 512
#define BT (Bsz*Tt)              // 1024
#define M_ALL (BT*NP)            // 51200
#define M_T (Bsz*(Tt-1)*NP)      // 50400
#define NEGV (-1000000000.0f)

// -------- static device scratch (no allocations allowed) --------
__device__ float g_x[(size_t)M_ALL*Hd];
__device__ float g_sp[(size_t)M_ALL*Hd];
__device__ float g_z[(size_t)M_ALL*Hd];
__device__ float g_tmp[(size_t)M_ALL*Hd];
__device__ float g_cos[M_T];

// row index r -> element offset of row start
// mode 0: dense rows of H
// mode 1: r enumerates (b, tt in [0,63), i in [0,50)); offset of (b, tt+shift, i)
__device__ __forceinline__ size_t row_off(int r, int mode, int shift) {
    if (mode == 0) return (size_t)r * Hd;
    int b   = r / ((Tt-1)*NP);
    int rem = r - b*(Tt-1)*NP;
    int tt  = rem / NP;
    int i   = rem - tt*NP;
    return ((size_t)((b*Tt + tt + shift)*NP) + i) * Hd;
}

// -------- concat(visual, audio) -> dense [BT*NP, H] --------
__global__ void concat_kernel(const float* __restrict__ vis,
                              const float* __restrict__ aud,
                              float* __restrict__ out) {
    size_t idx = (size_t)blockIdx.x * blockDim.x + threadIdx.x;   // float4 index
    size_t total = (size_t)M_ALL * (Hd/4);
    if (idx >= total) return;
    int h4 = (int)(idx & 127);
    size_t row = idx >> 7;
    int i = (int)(row % NP);
    size_t bt = row / NP;
    float4 v;
    if (i < NV) v = ((const float4*)vis)[(bt*NV + i)*(Hd/4) + h4];
    else        v = ((const float4*)aud)[bt*(Hd/4) + h4];
    ((float4*)out)[idx] = v;
}

// -------- generic SGEMM: C = epi(A(modes,scaled) @ W^T) --------
__global__ __launch_bounds__(256) void gemm512(
    const float* __restrict__ A, int amode, int ashift,
    const float* __restrict__ scale, int smode,      // 0 none, 1 s, 2 (1-s)
    const float* __restrict__ W,                     // [512,512] row-major
    const float* __restrict__ bias, int relu_flag,
    const float* __restrict__ add1, int a1mode, int a1shift,
    const float* __restrict__ add2,                  // dense row index
    float* __restrict__ C, int cmode, int cshift, int M)
{
    __shared__ float As[16][128];
    __shared__ float Bs[16][128];
    const int tid  = threadIdx.x;
    const int nb   = blockIdx.x;       // 0..3
    const int mb   = blockIdx.y;
    const int row0 = mb * 128;

    const int ar0 = tid >> 2;          // 0..63
    const int ac0 = (tid & 3) * 4;     // 0,4,8,12
    const int ar1 = ar0 + 64;

    int gr0 = row0 + ar0; if (gr0 >= M) gr0 = M - 1;
    int gr1 = row0 + ar1; if (gr1 >= M) gr1 = M - 1;
    const float* ap0 = A + row_off(gr0, amode, ashift) + ac0;
    const float* ap1 = A + row_off(gr1, amode, ashift) + ac0;
    float s0 = 1.f, s1 = 1.f;
    if (smode) {
        float v0 = scale[gr0], v1 = scale[gr1];
        if (smode == 1) { s0 = v0; s1 = v1; }
        else            { s0 = 1.f - v0; s1 = 1.f - v1; }
    }
    const float* wp0 = W + (size_t)(nb*128 + ar0)*Hd + ac0;
    const float* wp1 = W + (size_t)(nb*128 + ar1)*Hd + ac0;

    const int tx = tid & 15;   // n dir
    const int ty = tid >> 4;   // m dir
    float acc[8][8];
    #pragma unroll
    for (int i = 0; i < 8; i++)
        #pragma unroll
        for (int j = 0; j < 8; j++) acc[i][j] = 0.f;

    float4 ra0 = *(const float4*)(ap0);
    float4 ra1 = *(const float4*)(ap1);
    float4 rw0 = *(const float4*)(wp0);
    float4 rw1 = *(const float4*)(wp1);

    for (int k0 = 0; k0 < Hd; k0 += 16) {
        As[ac0+0][ar0] = ra0.x*s0; As[ac0+1][ar0] = ra0.y*s0;
        As[ac0+2][ar0] = ra0.z*s0; As[ac0+3][ar0] = ra0.w*s0;
        As[ac0+0][ar1] = ra1.x*s1; As[ac0+1][ar1] = ra1.y*s1;
        As[ac0+2][ar1] = ra1.z*s1; As[ac0+3][ar1] = ra1.w*s1;
        Bs[ac0+0][ar0] = rw0.x; Bs[ac0+1][ar0] = rw0.y;
        Bs[ac0+2][ar0] = rw0.z; Bs[ac0+3][ar0] = rw0.w;
        Bs[ac0+0][ar1] = rw1.x; Bs[ac0+1][ar1] = rw1.y;
        Bs[ac0+2][ar1] = rw1.z; Bs[ac0+3][ar1] = rw1.w;
        __syncthreads();
        if (k0 + 16 < Hd) {
            ra0 = *(const float4*)(ap0 + k0 + 16);
            ra1 = *(const float4*)(ap1 + k0 + 16);
            rw0 = *(const float4*)(wp0 + k0 + 16);
            rw1 = *(const float4*)(wp1 + k0 + 16);
        }
        #pragma unroll
        for (int kk = 0; kk < 16; kk++) {
            float af[8], bf[8];
            *(float4*)(af+0) = *(const float4*)&As[kk][ty*8+0];
            *(float4*)(af+4) = *(const float4*)&As[kk][ty*8+4];
            *(float4*)(bf+0) = *(const float4*)&Bs[kk][tx*8+0];
            *(float4*)(bf+4) = *(const float4*)&Bs[kk][tx*8+4];
            #pragma unroll
            for (int i = 0; i < 8; i++)
                #pragma unroll
                for (int j = 0; j < 8; j++)
                    acc[i][j] += af[i]*bf[j];
        }
        __syncthreads();
    }

    const int nbase = nb*128 + tx*8;
    #pragma unroll
    for (int im = 0; im < 8; im++) {
        int r = row0 + ty*8 + im;
        if (r >= M) continue;
        size_t co  = row_off(r, cmode, cshift);
        size_t a1o = add1 ? row_off(r, a1mode, a1shift) : 0;
        #pragma unroll
        for (int jn = 0; jn < 8; jn++) {
            int n = nbase + jn;
            float v = acc[im][jn];
            if (bias)      v += bias[n];
            if (relu_flag) v = fmaxf(v, 0.f);
            if (add1)      v += add1[a1o + n];
            if (add2)      v += add2[(size_t)r*Hd + n];
            C[co + n] = v;
        }
    }
}

// -------- fused attention + aggregation + LN + ReLU, one block per (b,t) --------
#define ATTN_SMEM_FLOATS (53*512 + 53*53 + 50*52 + 50 + 49 + 49 + 50 + 50 + 34)
#define ATTN_SMEM_BYTES  (ATTN_SMEM_FLOATS*4)

__global__ __launch_bounds__(512) void attn_agg_kernel(
    const float* __restrict__ X, const float* __restrict__ edge,
    const float* __restrict__ lng, const float* __restrict__ lnb,
    float* __restrict__ attn_out,      // nullable; [BT,50,50]
    float* __restrict__ spatial)
{
    extern __shared__ float sm[];
    float* Xs  = sm;                 // 53*512
    float* G   = Xs + 53*512;        // 53*53
    float* S   = G + 53*53;          // 50 rows, stride 52
    float* qn  = S + 50*52;          // 50
    float* kn0 = qn + 50;            // 49
    float* kn1 = kn0 + 49;           // 49
    float* sAv = kn1 + 49;           // 50
    float* a49 = sAv + 50;           // 50
    float* red = a49 + 50;           // 34

    const int bt   = blockIdx.x;
    const int tid  = threadIdx.x;
    const int lane = tid & 31, warp = tid >> 5;

    float4* Xs4 = (float4*)Xs;
    const float4* xg = (const float4*)(X + (size_t)bt*NP*Hd);
    const float4* eg = (const float4*)edge;
    for (int u = tid; u < 53*128; u += 512) {
        int row = u >> 7;
        Xs4[u] = (row < NP) ? xg[u] : eg[u - NP*128];
    }
    __syncthreads();

    // Gram over rows [x_0..x_49, e0, e1, e2], lower-triangular pairs
    for (int p = warp; p < 1431; p += 16) {
        int i = (int)((sqrtf(8.0f*p + 1.0f) - 1.0f) * 0.5f);
        while ((i+1)*(i+2)/2 <= p) ++i;
        while (i*(i+1)/2 > p)     --i;
        int j = p - i*(i+1)/2;
        const float4* xi = Xs4 + i*128;
        const float4* xj = Xs4 + j*128;
        float a = 0.f;
        for (int u = lane; u < 128; u += 32) {
            float4 p1 = xi[u], p2 = xj[u];
            a += p1.x*p2.x + p1.y*p2.y + p1.z*p2.z + p1.w*p2.w;
        }
        #pragma unroll
        for (int o = 16; o; o >>= 1) a += __shfl_xor_sync(0xffffffffu, a, o);
        if (lane == 0) { G[i*53+j] = a; G[j*53+i] = a; }
    }
    __syncthreads();

    if (tid < 50) qn[tid] = fmaxf(sqrtf(G[tid*53+tid]), 1e-12f);
    if (tid >= 64 && tid < 64+49) {
        int j = tid - 64;
        kn0[j] = fmaxf(sqrtf(G[j*53+j] + 2.f*G[j*53+50] + G[50*53+50]), 1e-12f);
    }
    if (tid >= 128 && tid < 128+49) {
        int j = tid - 128;
        kn1[j] = fmaxf(sqrtf(G[j*53+j] + 2.f*G[j*53+51] + G[51*53+51]), 1e-12f);
    }
    if (tid == 192)
        red[33] = fmaxf(sqrtf(G[49*53+49] + 2.f*G[49*53+52] + G[52*53+52]), 1e-12f);
    __syncthreads();
    const float kn2 = red[33];

    // scores
    for (int p = tid; p < 2500; p += 512) {
        int i = p / 50, j = p - (p/50)*50;
        float v;
        if (i == j)       v = NEGV;
        else if (j == 49) v = (G[i*53+49] + G[i*53+52]) / (qn[i]*kn2);
        else if (i == 49) v = (G[49*53+j] + G[49*53+51]) / (qn[49]*kn1[j]);
        else {
            int qr = i/7, qc = i - (i/7)*7, kr = j/7, kc = j - (j/7)*7;
            int r0 = (qr-1 > 0) ? qr-1 : 0;
            int c0 = qc-1; c0 = (c0 < 0) ? 0 : ((c0 > 4) ? 4 : c0);
            bool ok = (kr >= r0 && kr <= r0+2 && kc >= c0 && kc <= c0+2);
            v = ok ? (G[i*53+j] + G[i*53+50]) / (qn[i]*kn0[j]) : NEGV;
        }
        S[i*52+j] = v;
    }
    __syncthreads();

    // softmax: warp per row
    for (int i = warp; i < 50; i += 16) {
        float v0 = S[i*52 + lane];
        int j1 = lane + 32;
        float v1 = (j1 < 50) ? S[i*52 + j1] : -3.4e38f;
        float m = fmaxf(v0, v1);
        #pragma unroll
        for (int o = 16; o; o >>= 1) m = fmaxf(m, __shfl_xor_sync(0xffffffffu, m, o));
        float e0 = expf(v0 - m);
        float e1 = (j1 < 50) ? expf(v1 - m) : 0.f;
        float s = e0 + e1;
        #pragma unroll
        for (int o = 16; o; o >>= 1) s += __shfl_xor_sync(0xffffffffu, s, o);
        float e49 = __shfl_sync(0xffffffffu, e1, 17);  // j=49 lives at lane 17 slot 1
        float inv = 1.f / s;
        float p0 = e0 * inv, p1 = e1 * inv;
        S[i*52 + lane] = p0;
        if (j1 < 50) S[i*52 + j1] = p1;
        if (lane == 0) { sAv[i] = (s - e49)*inv; a49[i] = e49*inv; }
        if (attn_out) {
            attn_out[((size_t)bt*50 + i)*50 + lane] = p0;
            if (j1 < 50) attn_out[((size_t)bt*50 + i)*50 + j1] = p1;
        }
    }
    __syncthreads();

    // aggregation: thread owns feature h, 50 accumulators over nodes
    const int h = tid;
    float accv[50];
    #pragma unroll
    for (int i = 0; i < 50; i++) accv[i] = Xs[i*512 + h];
    for (int j = 0; j < 50; j++) {
        float xv = Xs[j*512 + h];
        #pragma unroll
        for (int i = 0; i < 50; i++) accv[i] += S[i*52 + j] * xv;
    }
    const float e0v = Xs[50*512 + h], e1v = Xs[51*512 + h], e2v = Xs[52*512 + h];
    const float gv = lng[h], bv = lnb[h];

    #pragma unroll
    for (int i = 0; i < 50; i++) {
        float v = accv[i] + sAv[i]*((i == 49) ? e1v : e0v) + a49[i]*e2v;
        float s1 = v, s2 = v*v;
        #pragma unroll
        for (int o = 16; o; o >>= 1) {
            s1 += __shfl_xor_sync(0xffffffffu, s1, o);
            s2 += __shfl_xor_sync(0xffffffffu, s2, o);
        }
        if (lane == 0) { red[warp] = s1; red[16+warp] = s2; }
        __syncthreads();
        if (warp == 0) {
            float a = (lane < 16) ? red[lane]    : 0.f;
            float c = (lane < 16) ? red[16+lane] : 0.f;
            #pragma unroll
            for (int o = 8; o; o >>= 1) {
                a += __shfl_xor_sync(0xffffffffu, a, o);
                c += __shfl_xor_sync(0xffffffffu, c, o);
            }
            if (lane == 0) {
                float mn = a * (1.f/512.f);
                red[32] = mn;
                red[33] = rsqrtf(c*(1.f/512.f) - mn*mn + 1e-5f);
            }
        }
        __syncthreads();
        float mn = red[32], rs = red[33];
        spatial[((size_t)bt*NP + i)*Hd + h] = fmaxf(0.f, (v - mn)*rs*gv + bv);
    }
}

// -------- cosine between spatial[t] and spatial[t-1], warp per (b,tt,i) --------
__global__ void cos_kernel(const float* __restrict__ sp,
                           float* __restrict__ c1, float* __restrict__ c2) {
    int gw = (int)((blockIdx.x*(size_t)blockDim.x + threadIdx.x) >> 5);
    int lane = threadIdx.x & 31;
    if (gw >= M_T) return;
    int b   = gw / ((Tt-1)*NP);
    int rem = gw - b*(Tt-1)*NP;
    int tt  = rem / NP;
    int i   = rem - tt*NP;
    const float4* pa = (const float4*)(sp + (((size_t)(b*Tt + tt + 1))*NP + i)*Hd);
    const float4* pb = (const float4*)(sp + (((size_t)(b*Tt + tt))*NP + i)*Hd);
    float d = 0.f, na = 0.f, nb2 = 0.f;
    for (int u = lane; u < 128; u += 32) {
        float4 a = pa[u], c = pb[u];
        d   += a.x*c.x + a.y*c.y + a.z*c.z + a.w*c.w;
        na  += a.x*a.x + a.y*a.y + a.z*a.z + a.w*a.w;
        nb2 += c.x*c.x + c.y*c.y + c.z*c.z + c.w*c.w;
    }
    #pragma unroll
    for (int o = 16; o; o >>= 1) {
        d   += __shfl_xor_sync(0xffffffffu, d, o);
        na  += __shfl_xor_sync(0xffffffffu, na, o);
        nb2 += __shfl_xor_sync(0xffffffffu, nb2, o);
    }
    if (lane == 0) {
        float v = d / (fmaxf(sqrtf(na), 1e-8f) * fmaxf(sqrtf(nb2), 1e-8f));
        c1[gw] = v;
        if (c2) c2[gw] = v;
    }
}

// -------- copy t=0 rows of spatial into z --------
__global__ void copy_t0(const float* __restrict__ sp, float* __restrict__ z) {
    int u = blockIdx.x*blockDim.x + threadIdx.x;  // float4 index over 16*50*128
    if (u >= Bsz*NP*(Hd/4)) return;
    int h4 = u & 127;
    int rem = u >> 7;
    int i = rem % NP;
    int b = rem / NP;
    size_t off = ((size_t)(b*Tt)*NP + i)*(Hd/4) + h4;
    ((float4*)z)[off] = ((const float4*)sp)[off];
}

// -------- LayerNorm rows of 512, block per row --------
__global__ __launch_bounds__(512) void ln512(const float* __restrict__ X,
                                             const float* __restrict__ g,
                                             const float* __restrict__ b,
                                             float* __restrict__ Y) {
    __shared__ float red[34];
    size_t base = (size_t)blockIdx.x * Hd;
    int tid = threadIdx.x, lane = tid & 31, warp = tid >> 5;
    float v = X[base + tid];
    float s1 = v, s2 = v*v;
    #pragma unroll
    for (int o = 16; o; o >>= 1) {
        s1 += __shfl_xor_sync(0xffffffffu, s1, o);
        s2 += __shfl_xor_sync(0xffffffffu, s2, o);
    }
    if (!lane) { red[warp] = s1; red[16+warp] = s2; }
    __syncthreads();
    if (warp == 0) {
        float a = (lane < 16) ? red[lane]    : 0.f;
        float c = (lane < 16) ? red[16+lane] : 0.f;
        #pragma unroll
        for (int o = 8; o; o >>= 1) {
            a += __shfl_xor_sync(0xffffffffu, a, o);
            c += __shfl_xor_sync(0xffffffffu, c, o);
        }
        if (!lane) {
            float m = a * (1.f/512.f);
            red[32] = m;
            red[33] = rsqrtf(c*(1.f/512.f) - m*m + 1e-5f);
        }
    }
    __syncthreads();
    Y[base + tid] = (v - red[32])*red[33]*g[tid] + b[tid];
}

extern "C" void kernel_launch(void* const* d_in, const int* in_sizes, int n_in,
                              void* d_out, int out_size) {
    (void)in_sizes; (void)n_in; (void)out_size;
    const float* vis   = (const float*)d_in[0];
    const float* aud   = (const float*)d_in[1];
    const float* in_W  = (const float*)d_in[2];
    const float* in_b  = (const float*)d_in[3];
    const float* out_W = (const float*)d_in[4];
    const float* out_b = (const float*)d_in[5];

    float* out      = (float*)d_out;
    float* attn_out = out + (size_t)M_ALL*Hd;                // 26,214,400
    float* cos_out  = attn_out + (size_t)BT*NP*NP;           // +2,560,000

    float *gx, *gsp, *gz, *gtmp, *gcos;
    cudaGetSymbolAddress((void**)&gx,   g_x);
    cudaGetSymbolAddress((void**)&gsp,  g_sp);
    cudaGetSymbolAddress((void**)&gz,   g_z);
    cudaGetSymbolAddress((void**)&gtmp, g_tmp);
    cudaGetSymbolAddress((void**)&gcos, g_cos);

    cudaFuncSetAttribute(attn_agg_kernel,
                         cudaFuncAttributeMaxDynamicSharedMemorySize, ATTN_SMEM_BYTES);

    // input projection
    concat_kernel<<<(M_ALL*128 + 255)/256, 256>>>(vis, aud, gz);
    dim3 gAll(4, (M_ALL + 127)/128);
    gemm512<<<gAll, 256>>>(gz, 0, 0, nullptr, 0, in_W, in_b, 0,
                           nullptr, 0, 0, nullptr, gx, 0, 0, M_ALL);

    for (int L = 0; L < 2; L++) {
        const float* edge = (const float*)d_in[6 + L*8];
        const float* lng  = (const float*)d_in[7 + L*8];
        const float* lnb  = (const float*)d_in[8 + L*8];
        const float* Wc   = (const float*)d_in[9 + L*8];
        const float* bc   = (const float*)d_in[10 + L*8];
        const float* Ws   = (const float*)d_in[11 + L*8];
        const float* bs   = (const float*)d_in[12 + L*8];
        const float* Wo   = (const float*)d_in[13 + L*8];

        attn_agg_kernel<<<BT, 512, ATTN_SMEM_BYTES>>>(
            gx, edge, lng, lnb, (L == 1) ? attn_out : nullptr, gsp);

        cos_kernel<<<(M_T*32 + 255)/256, 256>>>(gsp, gcos, (L == 1) ? cos_out : nullptr);

        dim3 gT(4, (M_T + 127)/128);
        // tc = relu(cos*prev @ Wc^T + bc) -> gtmp (dense rows)
        gemm512<<<gT, 256>>>(gsp, 1, 0, gcos, 1, Wc, bc, 1,
                             nullptr, 0, 0, nullptr, gtmp, 0, 0, M_T);
        // z[t+1] = cur + tc + relu((1-cos)*cur @ Ws^T + bs)
        gemm512<<<gT, 256>>>(gsp, 1, 1, gcos, 2, Ws, bs, 1,
                             gsp, 1, 1, gtmp, gz, 1, 1, M_T);
        copy_t0<<<(Bsz*NP*128 + 255)/256, 256>>>(gsp, gz);

        ln512<<<M_ALL, 512>>>(gz, lng, lnb, gtmp);
        // x = x + relu(LN(z) @ Wo^T)
        gemm512<<<gAll, 256>>>(gtmp, 0, 0, nullptr, 0, Wo, nullptr, 1,
                               gx, 0, 0, nullptr, gx, 0, 0, M_ALL);
    }

    // output projection
    gemm512<<<gAll, 256>>>(gx, 0, 0, nullptr, 0, out_W, out_b, 0,
                           nullptr, 0, 0, nullptr, out, 0, 0, M_ALL);
}

// round 3
// speedup vs baseline: 1.9098x; 1.9098x over previous
#include <cuda_runtime.h>
#include <math.h>
#include <cstdint>

#define Bsz 16
#define Tt 64
#define NV 49
#define NP 50
#define Hd 512
#define BT (Bsz*Tt)              // 1024
#define M_ALL (BT*NP)            // 51200
#define M_T (Bsz*(Tt-1)*NP)      // 50400
#define NEGV (-1000000000.0f)

// -------- static device scratch (no allocations allowed) --------
__device__ float g_x[(size_t)M_ALL*Hd];
__device__ float g_sp[(size_t)M_ALL*Hd];
__device__ float g_z[(size_t)M_ALL*Hd];
__device__ float g_tmp[(size_t)M_ALL*Hd];
__device__ float g_cos[M_T];
__device__ float g_wr[8][512*512];   // tf32-rounded weights

// row index r -> element offset of row start
__device__ __forceinline__ size_t row_off(int r, int mode, int shift) {
    if (mode == 0) return (size_t)r * Hd;
    int b   = r / ((Tt-1)*NP);
    int rem = r - b*(Tt-1)*NP;
    int tt  = rem / NP;
    int i   = rem - tt*NP;
    return ((size_t)((b*Tt + tt + shift)*NP) + i) * Hd;
}

__device__ __forceinline__ uint32_t f2tf(float f) {
    uint32_t r; asm("cvt.rna.tf32.f32 %0, %1;" : "=r"(r) : "f"(f)); return r;
}
__device__ __forceinline__ void cpa16(uint32_t dst, const void* src) {
    asm volatile("cp.async.cg.shared.global [%0], [%1], 16;" :: "r"(dst), "l"(src));
}
__device__ __forceinline__ uint32_t smem_u32(const void* p) {
    uint32_t a;
    asm("{ .reg .u64 t; cvta.to.shared.u64 t, %1; cvt.u32.u64 %0, t; }" : "=r"(a) : "l"(p));
    return a;
}

// -------- round f32 weights to tf32 (RN) once per launch --------
__global__ void round_tf32_k(const float* __restrict__ in, float* __restrict__ out) {
    int i = blockIdx.x * blockDim.x + threadIdx.x;
    out[i] = __uint_as_float(f2tf(in[i]));
}

// -------- concat(visual, audio) -> dense [BT*NP, H] --------
__global__ void concat_kernel(const float* __restrict__ vis,
                              const float* __restrict__ aud,
                              float* __restrict__ out) {
    size_t idx = (size_t)blockIdx.x * blockDim.x + threadIdx.x;
    size_t total = (size_t)M_ALL * (Hd/4);
    if (idx >= total) return;
    int h4 = (int)(idx & 127);
    size_t row = idx >> 7;
    int i = (int)(row % NP);
    size_t bt = row / NP;
    float4 v;
    if (i < NV) v = ((const float4*)vis)[(bt*NV + i)*(Hd/4) + h4];
    else        v = ((const float4*)aud)[bt*(Hd/4) + h4];
    ((float4*)out)[idx] = v;
}

// ============ tf32 mma.sync GEMM: C = epi(A @ W^T) ============
// CTA tile 128x128, K chunk 32, 2-stage cp.async pipeline.
// smem layout (floats, stride 36 per row): A0 | A1 | B0 | B1
#define SROW 36
#define STAGE_F (128*SROW)          // 4608 floats
#define GT_SMEM (4*STAGE_F*4)       // 73728 bytes

__global__ void __launch_bounds__(256, 2) gemm_tc(
    const float* __restrict__ A, int amode, int ashift,
    const float* __restrict__ scale, int smode,      // 0 none, 1 s, 2 (1-s)
    const float* __restrict__ W,                     // pre-rounded tf32 [512,512]
    const float* __restrict__ bias, int relu_flag,
    const float* __restrict__ add1, int a1mode, int a1shift,
    const float* __restrict__ add2,                  // dense row index
    float* __restrict__ C, int cmode, int cshift, int M)
{
    extern __shared__ float sm[];
    const int tid  = threadIdx.x;
    const int wid  = tid >> 5;
    const int lane = tid & 31;
    const int g    = lane >> 2;      // group 0..7
    const int tig  = lane & 3;       // 0..3
    const int wm   = wid & 1;        // 2 warps in m
    const int wn   = wid >> 1;       // 4 warps in n
    const int nb   = blockIdx.x;     // 0..3
    const int row0 = blockIdx.y * 128;

    // global load assignment: thread -> row (tid>>1), half (tid&1) of 32-float chunk
    const int ar = tid >> 1, ah = tid & 1;
    int gra = row0 + ar; if (gra >= M) gra = M - 1;
    const float* aptr = A + row_off(gra, amode, ashift) + ah*16;
    const float* bptr = W + (size_t)(nb*128 + ar)*Hd + ah*16;
    const uint32_t sm0 = smem_u32(sm);
    const uint32_t sa_addr = sm0 + (uint32_t)(ar*SROW + ah*16)*4;
    const uint32_t sb_addr = sm0 + (uint32_t)(2*STAGE_F + ar*SROW + ah*16)*4;

    auto CPAB = [&](int st, int k0) {
        uint32_t soff = (uint32_t)(st*STAGE_F)*4;
        #pragma unroll
        for (int j = 0; j < 4; j++)
            cpa16(sa_addr + soff + j*16, aptr + k0 + j*4);
        #pragma unroll
        for (int j = 0; j < 4; j++)
            cpa16(sb_addr + soff + j*16, bptr + k0 + j*4);
        asm volatile("cp.async.commit_group;" ::: "memory");
    };

    float acc[4][4][4];
    #pragma unroll
    for (int a = 0; a < 4; a++)
        #pragma unroll
        for (int b = 0; b < 4; b++)
            #pragma unroll
            for (int c = 0; c < 4; c++) acc[a][b][c] = 0.f;

    CPAB(0, 0);
    CPAB(1, 32);
    asm volatile("cp.async.wait_group 1;" ::: "memory");
    __syncthreads();

    const int NTILES = Hd/32;   // 16
    for (int kt = 0; kt < NTILES; kt++) {
        const int st = kt & 1;
        const float* As = sm + st*STAGE_F;
        const float* Bs = sm + 2*STAGE_F + st*STAGE_F;
        #pragma unroll
        for (int ks = 0; ks < 4; ks++) {
            uint32_t af[4][4];
            #pragma unroll
            for (int mt = 0; mt < 4; mt++) {
                const float* ap = As + (wm*64 + mt*16 + g)*SROW + ks*8 + tig;
                af[mt][0] = f2tf(ap[0]);
                af[mt][1] = f2tf(ap[8*SROW]);
                af[mt][2] = f2tf(ap[4]);
                af[mt][3] = f2tf(ap[8*SROW + 4]);
            }
            uint32_t bf[4][2];
            #pragma unroll
            for (int nt = 0; nt < 4; nt++) {
                const float* bp = Bs + (wn*32 + nt*8 + g)*SROW + ks*8 + tig;
                bf[nt][0] = __float_as_uint(bp[0]);
                bf[nt][1] = __float_as_uint(bp[4]);
            }
            #pragma unroll
            for (int mt = 0; mt < 4; mt++)
                #pragma unroll
                for (int nt = 0; nt < 4; nt++)
                    asm volatile(
                        "mma.sync.aligned.m16n8k8.row.col.f32.tf32.tf32.f32 "
                        "{%0,%1,%2,%3}, {%4,%5,%6,%7}, {%8,%9}, {%0,%1,%2,%3};"
                        : "+f"(acc[mt][nt][0]), "+f"(acc[mt][nt][1]),
                          "+f"(acc[mt][nt][2]), "+f"(acc[mt][nt][3])
                        : "r"(af[mt][0]), "r"(af[mt][1]), "r"(af[mt][2]), "r"(af[mt][3]),
                          "r"(bf[nt][0]), "r"(bf[nt][1]));
        }
        __syncthreads();
        if (kt + 2 < NTILES) CPAB(st, (kt+2)*32);
        if (kt + 1 < NTILES) {
            if (kt + 2 < NTILES) asm volatile("cp.async.wait_group 1;" ::: "memory");
            else                 asm volatile("cp.async.wait_group 0;" ::: "memory");
            __syncthreads();
        }
    }

    // -------- epilogue --------
    #pragma unroll
    for (int mt = 0; mt < 4; mt++) {
        #pragma unroll
        for (int hf = 0; hf < 2; hf++) {
            int r = row0 + wm*64 + mt*16 + g + hf*8;
            if (r >= M) continue;
            size_t co  = row_off(r, cmode, cshift);
            size_t a1o = add1 ? row_off(r, a1mode, a1shift) : 0;
            float sc = 1.f;
            if (smode) { float v = scale[r]; sc = (smode == 1) ? v : (1.f - v); }
            #pragma unroll
            for (int nt = 0; nt < 4; nt++) {
                int n = nb*128 + wn*32 + nt*8 + tig*2;
                float vx = acc[mt][nt][hf*2+0];
                float vy = acc[mt][nt][hf*2+1];
                if (smode) { vx *= sc; vy *= sc; }
                if (bias)  { vx += bias[n]; vy += bias[n+1]; }
                if (relu_flag) { vx = fmaxf(vx, 0.f); vy = fmaxf(vy, 0.f); }
                if (add1)  { vx += add1[a1o + n]; vy += add1[a1o + n + 1]; }
                if (add2)  { vx += add2[(size_t)r*Hd + n]; vy += add2[(size_t)r*Hd + n + 1]; }
                float2 o = make_float2(vx, vy);
                *(float2*)(C + co + n) = o;
            }
        }
    }
}

// -------- fused attention + aggregation + LN + ReLU, one block per (b,t) --------
#define ATTN_SMEM_FLOATS (53*512 + 53*53 + 50*52 + 50 + 49 + 49 + 50 + 50 + 34)
#define ATTN_SMEM_BYTES  (ATTN_SMEM_FLOATS*4)

__global__ __launch_bounds__(512) void attn_agg_kernel(
    const float* __restrict__ X, const float* __restrict__ edge,
    const float* __restrict__ lng, const float* __restrict__ lnb,
    float* __restrict__ attn_out, float* __restrict__ spatial)
{
    extern __shared__ float sm[];
    float* Xs  = sm;
    float* G   = Xs + 53*512;
    float* S   = G + 53*53;
    float* qn  = S + 50*52;
    float* kn0 = qn + 50;
    float* kn1 = kn0 + 49;
    float* sAv = kn1 + 49;
    float* a49 = sAv + 50;
    float* red = a49 + 50;

    const int bt   = blockIdx.x;
    const int tid  = threadIdx.x;
    const int lane = tid & 31, warp = tid >> 5;

    float4* Xs4 = (float4*)Xs;
    const float4* xg = (const float4*)(X + (size_t)bt*NP*Hd);
    const float4* eg = (const float4*)edge;
    for (int u = tid; u < 53*128; u += 512) {
        int row = u >> 7;
        Xs4[u] = (row < NP) ? xg[u] : eg[u - NP*128];
    }
    __syncthreads();

    for (int p = warp; p < 1431; p += 16) {
        int i = (int)((sqrtf(8.0f*p + 1.0f) - 1.0f) * 0.5f);
        while ((i+1)*(i+2)/2 <= p) ++i;
        while (i*(i+1)/2 > p)     --i;
        int j = p - i*(i+1)/2;
        const float4* xi = Xs4 + i*128;
        const float4* xj = Xs4 + j*128;
        float a = 0.f;
        for (int u = lane; u < 128; u += 32) {
            float4 p1 = xi[u], p2 = xj[u];
            a += p1.x*p2.x + p1.y*p2.y + p1.z*p2.z + p1.w*p2.w;
        }
        #pragma unroll
        for (int o = 16; o; o >>= 1) a += __shfl_xor_sync(0xffffffffu, a, o);
        if (lane == 0) { G[i*53+j] = a; G[j*53+i] = a; }
    }
    __syncthreads();

    if (tid < 50) qn[tid] = fmaxf(sqrtf(G[tid*53+tid]), 1e-12f);
    if (tid >= 64 && tid < 64+49) {
        int j = tid - 64;
        kn0[j] = fmaxf(sqrtf(G[j*53+j] + 2.f*G[j*53+50] + G[50*53+50]), 1e-12f);
    }
    if (tid >= 128 && tid < 128+49) {
        int j = tid - 128;
        kn1[j] = fmaxf(sqrtf(G[j*53+j] + 2.f*G[j*53+51] + G[51*53+51]), 1e-12f);
    }
    if (tid == 192)
        red[33] = fmaxf(sqrtf(G[49*53+49] + 2.f*G[49*53+52] + G[52*53+52]), 1e-12f);
    __syncthreads();
    const float kn2 = red[33];

    for (int p = tid; p < 2500; p += 512) {
        int i = p / 50, j = p - (p/50)*50;
        float v;
        if (i == j)       v = NEGV;
        else if (j == 49) v = (G[i*53+49] + G[i*53+52]) / (qn[i]*kn2);
        else if (i == 49) v = (G[49*53+j] + G[49*53+51]) / (qn[49]*kn1[j]);
        else {
            int qr = i/7, qc = i - (i/7)*7, kr = j/7, kc = j - (j/7)*7;
            int r0 = (qr-1 > 0) ? qr-1 : 0;
            int c0 = qc-1; c0 = (c0 < 0) ? 0 : ((c0 > 4) ? 4 : c0);
            bool ok = (kr >= r0 && kr <= r0+2 && kc >= c0 && kc <= c0+2);
            v = ok ? (G[i*53+j] + G[i*53+50]) / (qn[i]*kn0[j]) : NEGV;
        }
        S[i*52+j] = v;
    }
    __syncthreads();

    for (int i = warp; i < 50; i += 16) {
        float v0 = S[i*52 + lane];
        int j1 = lane + 32;
        float v1 = (j1 < 50) ? S[i*52 + j1] : -3.4e38f;
        float m = fmaxf(v0, v1);
        #pragma unroll
        for (int o = 16; o; o >>= 1) m = fmaxf(m, __shfl_xor_sync(0xffffffffu, m, o));
        float e0 = expf(v0 - m);
        float e1 = (j1 < 50) ? expf(v1 - m) : 0.f;
        float s = e0 + e1;
        #pragma unroll
        for (int o = 16; o; o >>= 1) s += __shfl_xor_sync(0xffffffffu, s, o);
        float e49 = __shfl_sync(0xffffffffu, e1, 17);
        float inv = 1.f / s;
        float p0 = e0 * inv, p1 = e1 * inv;
        S[i*52 + lane] = p0;
        if (j1 < 50) S[i*52 + j1] = p1;
        if (lane == 0) { sAv[i] = (s - e49)*inv; a49[i] = e49*inv; }
        if (attn_out) {
            attn_out[((size_t)bt*50 + i)*50 + lane] = p0;
            if (j1 < 50) attn_out[((size_t)bt*50 + i)*50 + j1] = p1;
        }
    }
    __syncthreads();

    const int h = tid;
    float accv[50];
    #pragma unroll
    for (int i = 0; i < 50; i++) accv[i] = Xs[i*512 + h];
    for (int j = 0; j < 50; j++) {
        float xv = Xs[j*512 + h];
        #pragma unroll
        for (int i = 0; i < 50; i++) accv[i] += S[i*52 + j] * xv;
    }
    const float e0v = Xs[50*512 + h], e1v = Xs[51*512 + h], e2v = Xs[52*512 + h];
    const float gv = lng[h], bv = lnb[h];

    #pragma unroll
    for (int i = 0; i < 50; i++) {
        float v = accv[i] + sAv[i]*((i == 49) ? e1v : e0v) + a49[i]*e2v;
        float s1 = v, s2 = v*v;
        #pragma unroll
        for (int o = 16; o; o >>= 1) {
            s1 += __shfl_xor_sync(0xffffffffu, s1, o);
            s2 += __shfl_xor_sync(0xffffffffu, s2, o);
        }
        if (lane == 0) { red[warp] = s1; red[16+warp] = s2; }
        __syncthreads();
        if (warp == 0) {
            float a = (lane < 16) ? red[lane]    : 0.f;
            float c = (lane < 16) ? red[16+lane] : 0.f;
            #pragma unroll
            for (int o = 8; o; o >>= 1) {
                a += __shfl_xor_sync(0xffffffffu, a, o);
                c += __shfl_xor_sync(0xffffffffu, c, o);
            }
            if (lane == 0) {
                float mn = a * (1.f/512.f);
                red[32] = mn;
                red[33] = rsqrtf(c*(1.f/512.f) - mn*mn + 1e-5f);
            }
        }
        __syncthreads();
        float mn = red[32], rs = red[33];
        spatial[((size_t)bt*NP + i)*Hd + h] = fmaxf(0.f, (v - mn)*rs*gv + bv);
    }
}

// -------- cosine between spatial[t] and spatial[t-1] --------
__global__ void cos_kernel(const float* __restrict__ sp,
                           float* __restrict__ c1, float* __restrict__ c2) {
    int gw = (int)((blockIdx.x*(size_t)blockDim.x + threadIdx.x) >> 5);
    int lane = threadIdx.x & 31;
    if (gw >= M_T) return;
    int b   = gw / ((Tt-1)*NP);
    int rem = gw - b*(Tt-1)*NP;
    int tt  = rem / NP;
    int i   = rem - tt*NP;
    const float4* pa = (const float4*)(sp + (((size_t)(b*Tt + tt + 1))*NP + i)*Hd);
    const float4* pb = (const float4*)(sp + (((size_t)(b*Tt + tt))*NP + i)*Hd);
    float d = 0.f, na = 0.f, nb2 = 0.f;
    for (int u = lane; u < 128; u += 32) {
        float4 a = pa[u], c = pb[u];
        d   += a.x*c.x + a.y*c.y + a.z*c.z + a.w*c.w;
        na  += a.x*a.x + a.y*a.y + a.z*a.z + a.w*a.w;
        nb2 += c.x*c.x + c.y*c.y + c.z*c.z + c.w*c.w;
    }
    #pragma unroll
    for (int o = 16; o; o >>= 1) {
        d   += __shfl_xor_sync(0xffffffffu, d, o);
        na  += __shfl_xor_sync(0xffffffffu, na, o);
        nb2 += __shfl_xor_sync(0xffffffffu, nb2, o);
    }
    if (lane == 0) {
        float v = d / (fmaxf(sqrtf(na), 1e-8f) * fmaxf(sqrtf(nb2), 1e-8f));
        c1[gw] = v;
        if (c2) c2[gw] = v;
    }
}

// -------- copy t=0 rows of spatial into z --------
__global__ void copy_t0(const float* __restrict__ sp, float* __restrict__ z) {
    int u = blockIdx.x*blockDim.x + threadIdx.x;
    if (u >= Bsz*NP*(Hd/4)) return;
    int h4 = u & 127;
    int rem = u >> 7;
    int i = rem % NP;
    int b = rem / NP;
    size_t off = ((size_t)(b*Tt)*NP + i)*(Hd/4) + h4;
    ((float4*)z)[off] = ((const float4*)sp)[off];
}

// -------- LayerNorm rows of 512, block per row --------
__global__ __launch_bounds__(512) void ln512(const float* __restrict__ X,
                                             const float* __restrict__ g,
                                             const float* __restrict__ b,
                                             float* __restrict__ Y) {
    __shared__ float red[34];
    size_t base = (size_t)blockIdx.x * Hd;
    int tid = threadIdx.x, lane = tid & 31, warp = tid >> 5;
    float v = X[base + tid];
    float s1 = v, s2 = v*v;
    #pragma unroll
    for (int o = 16; o; o >>= 1) {
        s1 += __shfl_xor_sync(0xffffffffu, s1, o);
        s2 += __shfl_xor_sync(0xffffffffu, s2, o);
    }
    if (!lane) { red[warp] = s1; red[16+warp] = s2; }
    __syncthreads();
    if (warp == 0) {
        float a = (lane < 16) ? red[lane]    : 0.f;
        float c = (lane < 16) ? red[16+lane] : 0.f;
        #pragma unroll
        for (int o = 8; o; o >>= 1) {
            a += __shfl_xor_sync(0xffffffffu, a, o);
            c += __shfl_xor_sync(0xffffffffu, c, o);
        }
        if (!lane) {
            float m = a * (1.f/512.f);
            red[32] = m;
            red[33] = rsqrtf(c*(1.f/512.f) - m*m + 1e-5f);
        }
    }
    __syncthreads();
    Y[base + tid] = (v - red[32])*red[33]*g[tid] + b[tid];
}

extern "C" void kernel_launch(void* const* d_in, const int* in_sizes, int n_in,
                              void* d_out, int out_size) {
    (void)in_sizes; (void)n_in; (void)out_size;
    const float* vis   = (const float*)d_in[0];
    const float* aud   = (const float*)d_in[1];
    const float* in_W  = (const float*)d_in[2];
    const float* in_b  = (const float*)d_in[3];
    const float* out_W = (const float*)d_in[4];
    const float* out_b = (const float*)d_in[5];

    float* out      = (float*)d_out;
    float* attn_out = out + (size_t)M_ALL*Hd;
    float* cos_out  = attn_out + (size_t)BT*NP*NP;

    float *gx, *gsp, *gz, *gtmp, *gcos, *gwr;
    cudaGetSymbolAddress((void**)&gx,   g_x);
    cudaGetSymbolAddress((void**)&gsp,  g_sp);
    cudaGetSymbolAddress((void**)&gz,   g_z);
    cudaGetSymbolAddress((void**)&gtmp, g_tmp);
    cudaGetSymbolAddress((void**)&gcos, g_cos);
    cudaGetSymbolAddress((void**)&gwr,  g_wr);

    cudaFuncSetAttribute(attn_agg_kernel,
                         cudaFuncAttributeMaxDynamicSharedMemorySize, ATTN_SMEM_BYTES);
    cudaFuncSetAttribute(gemm_tc,
                         cudaFuncAttributeMaxDynamicSharedMemorySize, GT_SMEM);

    // pre-round the 8 weight matrices to tf32 (RN)
    const float* wsrc[8] = {
        in_W, out_W,
        (const float*)d_in[9],  (const float*)d_in[11], (const float*)d_in[13],
        (const float*)d_in[17], (const float*)d_in[19], (const float*)d_in[21] };
    for (int i = 0; i < 8; i++)
        round_tf32_k<<<1024, 256>>>(wsrc[i], gwr + (size_t)i*512*512);
    const float* W_in  = gwr + 0*512*512;
    const float* W_out = gwr + 1*512*512;
    const float* W_l[2][3] = { { gwr+2*512*512, gwr+3*512*512, gwr+4*512*512 },
                               { gwr+5*512*512, gwr+6*512*512, gwr+7*512*512 } };

    // input projection
    concat_kernel<<<(M_ALL*128 + 255)/256, 256>>>(vis, aud, gz);
    dim3 gAll(4, (M_ALL + 127)/128);
    gemm_tc<<<gAll, 256, GT_SMEM>>>(gz, 0, 0, nullptr, 0, W_in, in_b, 0,
                                    nullptr, 0, 0, nullptr, gx, 0, 0, M_ALL);

    for (int L = 0; L < 2; L++) {
        const float* edge = (const float*)d_in[6 + L*8];
        const float* lng  = (const float*)d_in[7 + L*8];
        const float* lnb  = (const float*)d_in[8 + L*8];
        const float* bc   = (const float*)d_in[10 + L*8];
        const float* bs   = (const float*)d_in[12 + L*8];

        attn_agg_kernel<<<BT, 512, ATTN_SMEM_BYTES>>>(
            gx, edge, lng, lnb, (L == 1) ? attn_out : nullptr, gsp);

        cos_kernel<<<(M_T*32 + 255)/256, 256>>>(gsp, gcos, (L == 1) ? cos_out : nullptr);

        dim3 gT(4, (M_T + 127)/128);
        // tc = relu(cos * (prev @ Wc^T) + bc) -> gtmp (dense rows)
        gemm_tc<<<gT, 256, GT_SMEM>>>(gsp, 1, 0, gcos, 1, W_l[L][0], bc, 1,
                                      nullptr, 0, 0, nullptr, gtmp, 0, 0, M_T);
        // z[t+1] = cur + tc + relu((1-cos) * (cur @ Ws^T) + bs)
        gemm_tc<<<gT, 256, GT_SMEM>>>(gsp, 1, 1, gcos, 2, W_l[L][1], bs, 1,
                                      gsp, 1, 1, gtmp, gz, 1, 1, M_T);
        copy_t0<<<(Bsz*NP*128 + 255)/256, 256>>>(gsp, gz);

        ln512<<<M_ALL, 512>>>(gz, lng, lnb, gtmp);
        // x = x + relu(LN(z) @ Wo^T)
        gemm_tc<<<gAll, 256, GT_SMEM>>>(gtmp, 0, 0, nullptr, 0, W_l[L][2], nullptr, 1,
                                        gx, 0, 0, nullptr, gx, 0, 0, M_ALL);
    }

    // output projection
    gemm_tc<<<gAll, 256, GT_SMEM>>>(gx, 0, 0, nullptr, 0, W_out, out_b, 0,
                                    nullptr, 0, 0, nullptr, out, 0, 0, M_ALL);
}

// round 5
// speedup vs baseline: 2.1892x; 1.1463x over previous
#include <cuda_runtime.h>
#include <math.h>
#include <cstdint>

#define Bsz 16
#define Tt 64
#define NV 49
#define NP 50
#define Hd 512
#define BT (Bsz*Tt)              // 1024
#define M_ALL (BT*NP)            // 51200
#define M_T (Bsz*(Tt-1)*NP)      // 50400
#define NEGV (-1000000000.0f)

// -------- static device scratch (no allocations allowed) --------
__device__ float g_x[(size_t)M_ALL*Hd];
__device__ float g_sp[(size_t)M_ALL*Hd];
__device__ float g_z[(size_t)M_ALL*Hd];
__device__ float g_tmp[(size_t)M_ALL*Hd];
__device__ float g_cos[M_T];
__device__ float g_wr[8][512*512];   // tf32-rounded weights

__device__ __forceinline__ size_t row_off(int r, int mode, int shift) {
    if (mode == 0) return (size_t)r * Hd;
    int b   = r / ((Tt-1)*NP);
    int rem = r - b*(Tt-1)*NP;
    int tt  = rem / NP;
    int i   = rem - tt*NP;
    return ((size_t)((b*Tt + tt + shift)*NP) + i) * Hd;
}

__device__ __forceinline__ uint32_t f2tf(float f) {
    uint32_t r; asm("cvt.rna.tf32.f32 %0, %1;" : "=r"(r) : "f"(f)); return r;
}
__device__ __forceinline__ void cpa16(uint32_t dst, const void* src) {
    asm volatile("cp.async.cg.shared.global [%0], [%1], 16;" :: "r"(dst), "l"(src));
}
__device__ __forceinline__ uint32_t smem_u32(const void* p) {
    uint32_t a;
    asm("{ .reg .u64 t; cvta.to.shared.u64 t, %1; cvt.u32.u64 %0, t; }" : "=r"(a) : "l"(p));
    return a;
}
__device__ __forceinline__ void ldm4(uint32_t addr, uint32_t* r) {
    asm volatile("ldmatrix.sync.aligned.m8n8.x4.shared.b16 {%0,%1,%2,%3}, [%4];"
                 : "=r"(r[0]), "=r"(r[1]), "=r"(r[2]), "=r"(r[3]) : "r"(addr));
}

// -------- round all 8 f32 weight matrices to tf32 (RN), one launch --------
struct WPtrs { const float* p[8]; };
__global__ void round_tf32_k(WPtrs w, float* __restrict__ out) {
    size_t i = (size_t)blockIdx.x * blockDim.x + threadIdx.x;   // < 8*262144
    int m = (int)(i >> 18);
    int e = (int)(i & 0x3FFFF);
    out[i] = __uint_as_float(f2tf(w.p[m][e]));
}

// -------- concat(visual, audio) -> dense [BT*NP, H] --------
__global__ void concat_kernel(const float* __restrict__ vis,
                              const float* __restrict__ aud,
                              float* __restrict__ out) {
    size_t idx = (size_t)blockIdx.x * blockDim.x + threadIdx.x;
    size_t total = (size_t)M_ALL * (Hd/4);
    if (idx >= total) return;
    int h4 = (int)(idx & 127);
    size_t row = idx >> 7;
    int i = (int)(row % NP);
    size_t bt = row / NP;
    float4 v;
    if (i < NV) v = ((const float4*)vis)[(bt*NV + i)*(Hd/4) + h4];
    else        v = ((const float4*)aud)[bt*(Hd/4) + h4];
    ((float4*)out)[idx] = v;
}

// ============ tf32 mma.sync GEMM, ldmatrix frags, 3-stage pipeline ============
#define SROW 36
#define STAGE_F (128*SROW)          // 4608 floats
#define NSTAGE 3
#define GT_SMEM (2*NSTAGE*STAGE_F*4)   // 110592 bytes

__global__ void __launch_bounds__(256, 2) gemm_tc(
    const float* __restrict__ A, int amode, int ashift,
    const float* __restrict__ scale, int smode,      // 0 none, 1 s, 2 (1-s)
    const float* __restrict__ W,                     // pre-rounded tf32 [512,512]
    const float* __restrict__ bias, int relu_flag,
    const float* __restrict__ add1, int a1mode, int a1shift,
    const float* __restrict__ add2,                  // dense row index
    float* __restrict__ C, int cmode, int cshift, int M)
{
    extern __shared__ float sm[];
    const int tid  = threadIdx.x;
    const int wid  = tid >> 5;
    const int lane = tid & 31;
    const int tig  = lane & 3;       // 0..3
    const int wm   = wid & 1;        // 2 warps in m
    const int wn   = wid >> 1;       // 4 warps in n
    const int nb   = blockIdx.x;     // 0..3
    const int row0 = blockIdx.y * 128;
    const int g    = lane >> 2;      // used in epilogue row mapping

    // global->smem: thread -> row (tid>>1), half (tid&1) of 32-float chunk
    const int ar = tid >> 1, ah = tid & 1;
    int gra = row0 + ar; if (gra >= M) gra = M - 1;
    const float* aptr = A + row_off(gra, amode, ashift) + ah*16;
    const float* bptr = W + (size_t)(nb*128 + ar)*Hd + ah*16;
    const uint32_t sm0 = smem_u32(sm);
    const uint32_t sa_addr = sm0 + (uint32_t)(ar*SROW + ah*16)*4;
    const uint32_t sb_addr = sm0 + (uint32_t)(NSTAGE*STAGE_F + ar*SROW + ah*16)*4;

    auto CPAB = [&](int st, int k0) {
        uint32_t soff = (uint32_t)(st*STAGE_F)*4;
        #pragma unroll
        for (int j = 0; j < 4; j++)
            cpa16(sa_addr + soff + j*16, aptr + k0 + j*4);
        #pragma unroll
        for (int j = 0; j < 4; j++)
            cpa16(sb_addr + soff + j*16, bptr + k0 + j*4);
        asm volatile("cp.async.commit_group;" ::: "memory");
    };

    // ldmatrix per-lane base addresses (stage-relative)
    uint32_t la[4], lb[2];
    #pragma unroll
    for (int mt = 0; mt < 4; mt++)
        la[mt] = sm0 + (uint32_t)((wm*64 + mt*16 + (lane & 15))*SROW + ((lane >> 4) << 2))*4;
    #pragma unroll
    for (int ntp = 0; ntp < 2; ntp++)
        lb[ntp] = sm0 + (uint32_t)(NSTAGE*STAGE_F)*4
                + (uint32_t)((wn*32 + ntp*16 + ((lane & 16) >> 1) + (lane & 7))*SROW
                             + (((lane >> 3) & 1) << 2))*4;

    float acc[4][4][4];
    #pragma unroll
    for (int a = 0; a < 4; a++)
        #pragma unroll
        for (int b = 0; b < 4; b++)
            #pragma unroll
            for (int c = 0; c < 4; c++) acc[a][b][c] = 0.f;

    CPAB(0, 0);
    CPAB(1, 32);

    const int NTILES = Hd/32;   // 16
    for (int kt = 0; kt < NTILES; kt++) {
        const int st = kt % NSTAGE;
        const uint32_t soff = (uint32_t)(st*STAGE_F)*4;
        if (kt + 1 < NTILES) asm volatile("cp.async.wait_group 1;" ::: "memory");
        else                 asm volatile("cp.async.wait_group 0;" ::: "memory");
        __syncthreads();
        #pragma unroll
        for (int ks = 0; ks < 4; ks++) {
            const uint32_t kb = soff + ks*32;
            uint32_t af[4][4];
            #pragma unroll
            for (int mt = 0; mt < 4; mt++) {
                ldm4(la[mt] + kb, af[mt]);
                af[mt][0] = f2tf(__uint_as_float(af[mt][0]));
                af[mt][1] = f2tf(__uint_as_float(af[mt][1]));
                af[mt][2] = f2tf(__uint_as_float(af[mt][2]));
                af[mt][3] = f2tf(__uint_as_float(af[mt][3]));
            }
            uint32_t bf[2][4];
            #pragma unroll
            for (int ntp = 0; ntp < 2; ntp++)
                ldm4(lb[ntp] + kb, bf[ntp]);
            #pragma unroll
            for (int mt = 0; mt < 4; mt++)
                #pragma unroll
                for (int nt = 0; nt < 4; nt++) {
                    const int ntp = nt >> 1, hb = (nt & 1) * 2;
                    asm volatile(
                        "mma.sync.aligned.m16n8k8.row.col.f32.tf32.tf32.f32 "
                        "{%0,%1,%2,%3}, {%4,%5,%6,%7}, {%8,%9}, {%0,%1,%2,%3};"
                        : "+f"(acc[mt][nt][0]), "+f"(acc[mt][nt][1]),
                          "+f"(acc[mt][nt][2]), "+f"(acc[mt][nt][3])
                        : "r"(af[mt][0]), "r"(af[mt][1]), "r"(af[mt][2]), "r"(af[mt][3]),
                          "r"(bf[ntp][hb]), "r"(bf[ntp][hb+1]));
                }
        }
        if (kt + 2 < NTILES) CPAB((kt + 2) % NSTAGE, (kt + 2) * 32);
    }

    // -------- epilogue --------
    #pragma unroll
    for (int mt = 0; mt < 4; mt++) {
        #pragma unroll
        for (int hf = 0; hf < 2; hf++) {
            int r = row0 + wm*64 + mt*16 + g + hf*8;
            if (r >= M) continue;
            size_t co  = row_off(r, cmode, cshift);
            size_t a1o = add1 ? row_off(r, a1mode, a1shift) : 0;
            float sc = 1.f;
            if (smode) { float v = scale[r]; sc = (smode == 1) ? v : (1.f - v); }
            #pragma unroll
            for (int nt = 0; nt < 4; nt++) {
                int n = nb*128 + wn*32 + nt*8 + tig*2;
                float vx = acc[mt][nt][hf*2+0];
                float vy = acc[mt][nt][hf*2+1];
                if (smode) { vx *= sc; vy *= sc; }
                if (bias)  { vx += bias[n]; vy += bias[n+1]; }
                if (relu_flag) { vx = fmaxf(vx, 0.f); vy = fmaxf(vy, 0.f); }
                if (add1)  { vx += add1[a1o + n]; vy += add1[a1o + n + 1]; }
                if (add2)  { vx += add2[(size_t)r*Hd + n]; vy += add2[(size_t)r*Hd + n + 1]; }
                float2 o = make_float2(vx, vy);
                *(float2*)(C + co + n) = o;
            }
        }
    }
}

// -------- fused attention + aggregation + LN + ReLU, one block per (b,t) --------
#define ATTN_SMEM_FLOATS (53*512 + 53*53 + 50*52 + 50 + 49 + 49 + 50 + 50 + 34)
#define ATTN_SMEM_BYTES  (ATTN_SMEM_FLOATS*4)

__global__ __launch_bounds__(512) void attn_agg_kernel(
    const float* __restrict__ X, const float* __restrict__ edge,
    const float* __restrict__ lng, const float* __restrict__ lnb,
    float* __restrict__ attn_out, float* __restrict__ spatial)
{
    extern __shared__ float sm[];
    float* Xs  = sm;
    float* G   = Xs + 53*512;
    float* S   = G + 53*53;
    float* qn  = S + 50*52;
    float* kn0 = qn + 50;
    float* kn1 = kn0 + 49;
    float* sAv = kn1 + 49;
    float* a49 = sAv + 50;
    float* red = a49 + 50;

    const int bt   = blockIdx.x;
    const int tid  = threadIdx.x;
    const int lane = tid & 31, warp = tid >> 5;

    float4* Xs4 = (float4*)Xs;
    const float4* xg = (const float4*)(X + (size_t)bt*NP*Hd);
    const float4* eg = (const float4*)edge;
    for (int u = tid; u < 53*128; u += 512) {
        int row = u >> 7;
        Xs4[u] = (row < NP) ? xg[u] : eg[u - NP*128];
    }
    __syncthreads();

    for (int p = warp; p < 1431; p += 16) {
        int i = (int)((sqrtf(8.0f*p + 1.0f) - 1.0f) * 0.5f);
        while ((i+1)*(i+2)/2 <= p) ++i;
        while (i*(i+1)/2 > p)     --i;
        int j = p - i*(i+1)/2;
        const float4* xi = Xs4 + i*128;
        const float4* xj = Xs4 + j*128;
        float a = 0.f;
        for (int u = lane; u < 128; u += 32) {
            float4 p1 = xi[u], p2 = xj[u];
            a += p1.x*p2.x + p1.y*p2.y + p1.z*p2.z + p1.w*p2.w;
        }
        #pragma unroll
        for (int o = 16; o; o >>= 1) a += __shfl_xor_sync(0xffffffffu, a, o);
        if (lane == 0) { G[i*53+j] = a; G[j*53+i] = a; }
    }
    __syncthreads();

    if (tid < 50) qn[tid] = fmaxf(sqrtf(G[tid*53+tid]), 1e-12f);
    if (tid >= 64 && tid < 64+49) {
        int j = tid - 64;
        kn0[j] = fmaxf(sqrtf(G[j*53+j] + 2.f*G[j*53+50] + G[50*53+50]), 1e-12f);
    }
    if (tid >= 128 && tid < 128+49) {
        int j = tid - 128;
        kn1[j] = fmaxf(sqrtf(G[j*53+j] + 2.f*G[j*53+51] + G[51*53+51]), 1e-12f);
    }
    if (tid == 192)
        red[33] = fmaxf(sqrtf(G[49*53+49] + 2.f*G[49*53+52] + G[52*53+52]), 1e-12f);
    __syncthreads();
    const float kn2 = red[33];

    for (int p = tid; p < 2500; p += 512) {
        int i = p / 50, j = p - (p/50)*50;
        float v;
        if (i == j)       v = NEGV;
        else if (j == 49) v = (G[i*53+49] + G[i*53+52]) / (qn[i]*kn2);
        else if (i == 49) v = (G[49*53+j] + G[49*53+51]) / (qn[49]*kn1[j]);
        else {
            int qr = i/7, qc = i - (i/7)*7, kr = j/7, kc = j - (j/7)*7;
            int r0 = (qr-1 > 0) ? qr-1 : 0;
            int c0 = qc-1; c0 = (c0 < 0) ? 0 : ((c0 > 4) ? 4 : c0);
            bool ok = (kr >= r0 && kr <= r0+2 && kc >= c0 && kc <= c0+2);
            v = ok ? (G[i*53+j] + G[i*53+50]) / (qn[i]*kn0[j]) : NEGV;
        }
        S[i*52+j] = v;
    }
    __syncthreads();

    for (int i = warp; i < 50; i += 16) {
        float v0 = S[i*52 + lane];
        int j1 = lane + 32;
        float v1 = (j1 < 50) ? S[i*52 + j1] : -3.4e38f;
        float m = fmaxf(v0, v1);
        #pragma unroll
        for (int o = 16; o; o >>= 1) m = fmaxf(m, __shfl_xor_sync(0xffffffffu, m, o));
        float e0 = expf(v0 - m);
        float e1 = (j1 < 50) ? expf(v1 - m) : 0.f;
        float s = e0 + e1;
        #pragma unroll
        for (int o = 16; o; o >>= 1) s += __shfl_xor_sync(0xffffffffu, s, o);
        float e49 = __shfl_sync(0xffffffffu, e1, 17);
        float inv = 1.f / s;
        float p0 = e0 * inv, p1 = e1 * inv;
        S[i*52 + lane] = p0;
        if (j1 < 50) S[i*52 + j1] = p1;
        if (lane == 0) { sAv[i] = (s - e49)*inv; a49[i] = e49*inv; }
        if (attn_out) {
            attn_out[((size_t)bt*50 + i)*50 + lane] = p0;
            if (j1 < 50) attn_out[((size_t)bt*50 + i)*50 + j1] = p1;
        }
    }
    __syncthreads();

    // aggregation: thread owns feature h
    const int h = tid;
    float accv[50];
    #pragma unroll
    for (int i = 0; i < 50; i++) accv[i] = Xs[i*512 + h];
    for (int j = 0; j < 50; j++) {
        float xv = Xs[j*512 + h];
        #pragma unroll
        for (int i = 0; i < 50; i++) accv[i] += S[i*52 + j] * xv;
    }
    const float e0v = Xs[50*512 + h], e1v = Xs[51*512 + h], e2v = Xs[52*512 + h];
    #pragma unroll
    for (int i = 0; i < 50; i++)
        accv[i] += sAv[i]*((i == 49) ? e1v : e0v) + a49[i]*e2v;

    __syncthreads();   // all reads of Xs rows 0..49 and S done
    // stash v into Xs (rows 0..49) and LN params into S (no longer needed)
    #pragma unroll
    for (int i = 0; i < 50; i++) Xs[i*512 + h] = accv[i];
    S[tid]       = lng[tid];
    S[512 + tid] = lnb[tid];
    __syncthreads();

    // per-warp LayerNorm+ReLU rows
    for (int i = warp; i < 50; i += 16) {
        float s1 = 0.f, s2 = 0.f;
        #pragma unroll
        for (int k = 0; k < 16; k++) {
            float v = Xs[i*512 + lane + k*32];
            s1 += v; s2 += v*v;
        }
        #pragma unroll
        for (int o = 16; o; o >>= 1) {
            s1 += __shfl_xor_sync(0xffffffffu, s1, o);
            s2 += __shfl_xor_sync(0xffffffffu, s2, o);
        }
        float mn = s1 * (1.f/512.f);
        float rs = rsqrtf(s2*(1.f/512.f) - mn*mn + 1e-5f);
        float* dst = spatial + ((size_t)bt*NP + i)*Hd;
        #pragma unroll
        for (int k = 0; k < 16; k++) {
            int u = lane + k*32;
            float v = Xs[i*512 + u];
            dst[u] = fmaxf(0.f, (v - mn)*rs*S[u] + S[512 + u]);
        }
    }
}

// -------- cosine between spatial[t] and spatial[t-1] --------
__global__ void cos_kernel(const float* __restrict__ sp,
                           float* __restrict__ c1, float* __restrict__ c2) {
    int gw = (int)((blockIdx.x*(size_t)blockDim.x + threadIdx.x) >> 5);
    int lane = threadIdx.x & 31;
    if (gw >= M_T) return;
    int b   = gw / ((Tt-1)*NP);
    int rem = gw - b*(Tt-1)*NP;
    int tt  = rem / NP;
    int i   = rem - tt*NP;
    const float4* pa = (const float4*)(sp + (((size_t)(b*Tt + tt + 1))*NP + i)*Hd);
    const float4* pb = (const float4*)(sp + (((size_t)(b*Tt + tt))*NP + i)*Hd);
    float d = 0.f, na = 0.f, nb2 = 0.f;
    for (int u = lane; u < 128; u += 32) {
        float4 a = pa[u], c = pb[u];
        d   += a.x*c.x + a.y*c.y + a.z*c.z + a.w*c.w;
        na  += a.x*a.x + a.y*a.y + a.z*a.z + a.w*a.w;
        nb2 += c.x*c.x + c.y*c.y + c.z*c.z + c.w*c.w;
    }
    #pragma unroll
    for (int o = 16; o; o >>= 1) {
        d   += __shfl_xor_sync(0xffffffffu, d, o);
        na  += __shfl_xor_sync(0xffffffffu, na, o);
        nb2 += __shfl_xor_sync(0xffffffffu, nb2, o);
    }
    if (lane == 0) {
        float v = d / (fmaxf(sqrtf(na), 1e-8f) * fmaxf(sqrtf(nb2), 1e-8f));
        c1[gw] = v;
        if (c2) c2[gw] = v;
    }
}

// -------- copy t=0 rows of spatial into z --------
__global__ void copy_t0(const float* __restrict__ sp, float* __restrict__ z) {
    int u = blockIdx.x*blockDim.x + threadIdx.x;
    if (u >= Bsz*NP*(Hd/4)) return;
    int h4 = u & 127;
    int rem = u >> 7;
    int i = rem % NP;
    int b = rem / NP;
    size_t off = ((size_t)(b*Tt)*NP + i)*(Hd/4) + h4;
    ((float4*)z)[off] = ((const float4*)sp)[off];
}

// -------- LayerNorm rows of 512, block per row --------
__global__ __launch_bounds__(512) void ln512(const float* __restrict__ X,
                                             const float* __restrict__ g,
                                             const float* __restrict__ b,
                                             float* __restrict__ Y) {
    __shared__ float red[34];
    size_t base = (size_t)blockIdx.x * Hd;
    int tid = threadIdx.x, lane = tid & 31, warp = tid >> 5;
    float v = X[base + tid];
    float s1 = v, s2 = v*v;
    #pragma unroll
    for (int o = 16; o; o >>= 1) {
        s1 += __shfl_xor_sync(0xffffffffu, s1, o);
        s2 += __shfl_xor_sync(0xffffffffu, s2, o);
    }
    if (!lane) { red[warp] = s1; red[16+warp] = s2; }
    __syncthreads();
    if (warp == 0) {
        float a = (lane < 16) ? red[lane]    : 0.f;
        float c = (lane < 16) ? red[16+lane] : 0.f;
        #pragma unroll
        for (int o = 8; o; o >>= 1) {
            a += __shfl_xor_sync(0xffffffffu, a, o);
            c += __shfl_xor_sync(0xffffffffu, c, o);
        }
        if (!lane) {
            float m = a * (1.f/512.f);
            red[32] = m;
            red[33] = rsqrtf(c*(1.f/512.f) - m*m + 1e-5f);
        }
    }
    __syncthreads();
    Y[base + tid] = (v - red[32])*red[33]*g[tid] + b[tid];
}

extern "C" void kernel_launch(void* const* d_in, const int* in_sizes, int n_in,
                              void* d_out, int out_size) {
    (void)in_sizes; (void)n_in; (void)out_size;
    const float* vis   = (const float*)d_in[0];
    const float* aud   = (const float*)d_in[1];
    const float* in_W  = (const float*)d_in[2];
    const float* in_b  = (const float*)d_in[3];
    const float* out_W = (const float*)d_in[4];
    const float* out_b = (const float*)d_in[5];

    float* out      = (float*)d_out;
    float* attn_out = out + (size_t)M_ALL*Hd;
    float* cos_out  = attn_out + (size_t)BT*NP*NP;

    float *gx, *gsp, *gz, *gtmp, *gcos, *gwr;
    cudaGetSymbolAddress((void**)&gx,   g_x);
    cudaGetSymbolAddress((void**)&gsp,  g_sp);
    cudaGetSymbolAddress((void**)&gz,   g_z);
    cudaGetSymbolAddress((void**)&gtmp, g_tmp);
    cudaGetSymbolAddress((void**)&gcos, g_cos);
    cudaGetSymbolAddress((void**)&gwr,  g_wr);

    cudaFuncSetAttribute(attn_agg_kernel,
                         cudaFuncAttributeMaxDynamicSharedMemorySize, ATTN_SMEM_BYTES);
    cudaFuncSetAttribute(gemm_tc,
                         cudaFuncAttributeMaxDynamicSharedMemorySize, GT_SMEM);

    // pre-round the 8 weight matrices to tf32 (RN), one launch
    WPtrs wp;
    wp.p[0] = in_W;  wp.p[1] = out_W;
    wp.p[2] = (const float*)d_in[9];  wp.p[3] = (const float*)d_in[11];
    wp.p[4] = (const float*)d_in[13]; wp.p[5] = (const float*)d_in[17];
    wp.p[6] = (const float*)d_in[19]; wp.p[7] = (const float*)d_in[21];
    round_tf32_k<<<8192, 256>>>(wp, gwr);
    const float* W_in  = gwr + 0*512*512;
    const float* W_out = gwr + (size_t)1*512*512;
    const float* W_l[2][3] = { { gwr+(size_t)2*512*512, gwr+(size_t)3*512*512, gwr+(size_t)4*512*512 },
                               { gwr+(size_t)5*512*512, gwr+(size_t)6*512*512, gwr+(size_t)7*512*512 } };

    // input projection
    concat_kernel<<<(M_ALL*128 + 255)/256, 256>>>(vis, aud, gz);
    dim3 gAll(4, (M_ALL + 127)/128);
    gemm_tc<<<gAll, 256, GT_SMEM>>>(gz, 0, 0, nullptr, 0, W_in, in_b, 0,
                                    nullptr, 0, 0, nullptr, gx, 0, 0, M_ALL);

    for (int L = 0; L < 2; L++) {
        const float* edge = (const float*)d_in[6 + L*8];
        const float* lng  = (const float*)d_in[7 + L*8];
        const float* lnb  = (const float*)d_in[8 + L*8];
        const float* bc   = (const float*)d_in[10 + L*8];
        const float* bs   = (const float*)d_in[12 + L*8];

        attn_agg_kernel<<<BT, 512, ATTN_SMEM_BYTES>>>(
            gx, edge, lng, lnb, (L == 1) ? attn_out : nullptr, gsp);

        cos_kernel<<<(M_T*32 + 255)/256, 256>>>(gsp, gcos, (L == 1) ? cos_out : nullptr);

        dim3 gT(4, (M_T + 127)/128);
        // tc = relu(cos * (prev @ Wc^T) + bc) -> gtmp (dense rows)
        gemm_tc<<<gT, 256, GT_SMEM>>>(gsp, 1, 0, gcos, 1, W_l[L][0], bc, 1,
                                      nullptr, 0, 0, nullptr, gtmp, 0, 0, M_T);
        // z[t+1] = cur + tc + relu((1-cos) * (cur @ Ws^T) + bs)
        gemm_tc<<<gT, 256, GT_SMEM>>>(gsp, 1, 1, gcos, 2, W_l[L][1], bs, 1,
                                      gsp, 1, 1, gtmp, gz, 1, 1, M_T);
        copy_t0<<<(Bsz*NP*128 + 255)/256, 256>>>(gsp, gz);

        ln512<<<M_ALL, 512>>>(gz, lng, lnb, gtmp);
        // x = x + relu(LN(z) @ Wo^T)
        gemm_tc<<<gAll, 256, GT_SMEM>>>(gtmp, 0, 0, nullptr, 0, W_l[L][2], nullptr, 1,
                                        gx, 0, 0, nullptr, gx, 0, 0, M_ALL);
    }

    // output projection
    gemm_tc<<<gAll, 256, GT_SMEM>>>(gx, 0, 0, nullptr, 0, W_out, out_b, 0,
                                    nullptr, 0, 0, nullptr, out, 0, 0, M_ALL);
}

// round 6
// speedup vs baseline: 2.2482x; 1.0269x over previous
#include <cuda_runtime.h>
#include <math.h>
#include <cstdint>

#define Bsz 16
#define Tt 64
#define NV 49
#define NP 50
#define Hd 512
#define BT (Bsz*Tt)              // 1024
#define M_ALL (BT*NP)            // 51200
#define M_T (Bsz*(Tt-1)*NP)      // 50400
#define NEGV (-1000000000.0f)

// -------- static device scratch (no allocations allowed) --------
__device__ float g_x[(size_t)M_ALL*Hd];
__device__ float g_sp[(size_t)M_ALL*Hd];
__device__ float g_z[(size_t)M_ALL*Hd];
__device__ float g_tmp[(size_t)M_ALL*Hd];
__device__ float g_cos[M_T];
__device__ float g_wr[8][512*512];   // tf32-rounded weights

__device__ __forceinline__ size_t row_off(int r, int mode, int shift) {
    if (mode == 0) return (size_t)r * Hd;
    int b   = r / ((Tt-1)*NP);
    int rem = r - b*(Tt-1)*NP;
    int tt  = rem / NP;
    int i   = rem - tt*NP;
    return ((size_t)((b*Tt + tt + shift)*NP) + i) * Hd;
}

__device__ __forceinline__ uint32_t f2tf(float f) {
    uint32_t r; asm("cvt.rna.tf32.f32 %0, %1;" : "=r"(r) : "f"(f)); return r;
}
__device__ __forceinline__ void cpa16(uint32_t dst, const void* src) {
    asm volatile("cp.async.cg.shared.global [%0], [%1], 16;" :: "r"(dst), "l"(src));
}
__device__ __forceinline__ uint32_t smem_u32(const void* p) {
    uint32_t a;
    asm("{ .reg .u64 t; cvta.to.shared.u64 t, %1; cvt.u32.u64 %0, t; }" : "=r"(a) : "l"(p));
    return a;
}
__device__ __forceinline__ void ldm4(uint32_t addr, uint32_t* r) {
    asm volatile("ldmatrix.sync.aligned.m8n8.x4.shared.b16 {%0,%1,%2,%3}, [%4];"
                 : "=r"(r[0]), "=r"(r[1]), "=r"(r[2]), "=r"(r[3]) : "r"(addr));
}

// -------- round all 8 f32 weight matrices to tf32 (RN), one launch --------
struct WPtrs { const float* p[8]; };
__global__ void round_tf32_k(WPtrs w, float* __restrict__ out) {
    size_t i = (size_t)blockIdx.x * blockDim.x + threadIdx.x;   // < 8*262144
    int m = (int)(i >> 18);
    int e = (int)(i & 0x3FFFF);
    out[i] = __uint_as_float(f2tf(w.p[m][e]));
}

// -------- concat(visual, audio) -> dense [BT*NP, H] --------
__global__ void concat_kernel(const float* __restrict__ vis,
                              const float* __restrict__ aud,
                              float* __restrict__ out) {
    size_t idx = (size_t)blockIdx.x * blockDim.x + threadIdx.x;
    size_t total = (size_t)M_ALL * (Hd/4);
    if (idx >= total) return;
    int h4 = (int)(idx & 127);
    size_t row = idx >> 7;
    int i = (int)(row % NP);
    size_t bt = row / NP;
    float4 v;
    if (i < NV) v = ((const float4*)vis)[(bt*NV + i)*(Hd/4) + h4];
    else        v = ((const float4*)aud)[bt*(Hd/4) + h4];
    ((float4*)out)[idx] = v;
}

// ============ tf32 mma.sync GEMM, ldmatrix frags, 3-stage pipeline ============
#define SROW 36
#define STAGE_F (128*SROW)          // 4608 floats
#define NSTAGE 3
#define GT_SMEM (2*NSTAGE*STAGE_F*4)   // 110592 bytes

__global__ void __launch_bounds__(256, 2) gemm_tc(
    const float* __restrict__ A, int amode, int ashift,
    const float* __restrict__ scale, int smode,      // 0 none, 1 s, 2 (1-s)
    const float* __restrict__ W,                     // pre-rounded tf32 [512,512]
    const float* __restrict__ bias, int relu_flag,
    const float* __restrict__ add1, int a1mode, int a1shift,
    const float* __restrict__ add2,                  // dense row index
    float* __restrict__ C, int cmode, int cshift, int M)
{
    extern __shared__ float sm[];
    const int tid  = threadIdx.x;
    const int wid  = tid >> 5;
    const int lane = tid & 31;
    const int tig  = lane & 3;       // 0..3
    const int wm   = wid & 1;        // 2 warps in m
    const int wn   = wid >> 1;       // 4 warps in n
    const int nb   = blockIdx.x;     // 0..3
    const int row0 = blockIdx.y * 128;
    const int g    = lane >> 2;      // used in epilogue row mapping

    // global->smem: thread -> row (tid>>1), half (tid&1) of 32-float chunk
    const int ar = tid >> 1, ah = tid & 1;
    int gra = row0 + ar; if (gra >= M) gra = M - 1;
    const float* aptr = A + row_off(gra, amode, ashift) + ah*16;
    const float* bptr = W + (size_t)(nb*128 + ar)*Hd + ah*16;
    const uint32_t sm0 = smem_u32(sm);
    const uint32_t sa_addr = sm0 + (uint32_t)(ar*SROW + ah*16)*4;
    const uint32_t sb_addr = sm0 + (uint32_t)(NSTAGE*STAGE_F + ar*SROW + ah*16)*4;

    auto CPAB = [&](int st, int k0) {
        uint32_t soff = (uint32_t)(st*STAGE_F)*4;
        #pragma unroll
        for (int j = 0; j < 4; j++)
            cpa16(sa_addr + soff + j*16, aptr + k0 + j*4);
        #pragma unroll
        for (int j = 0; j < 4; j++)
            cpa16(sb_addr + soff + j*16, bptr + k0 + j*4);
        asm volatile("cp.async.commit_group;" ::: "memory");
    };

    // ldmatrix per-lane base addresses (stage-relative)
    uint32_t la[4], lb[2];
    #pragma unroll
    for (int mt = 0; mt < 4; mt++)
        la[mt] = sm0 + (uint32_t)((wm*64 + mt*16 + (lane & 15))*SROW + ((lane >> 4) << 2))*4;
    #pragma unroll
    for (int ntp = 0; ntp < 2; ntp++)
        lb[ntp] = sm0 + (uint32_t)(NSTAGE*STAGE_F)*4
                + (uint32_t)((wn*32 + ntp*16 + ((lane & 16) >> 1) + (lane & 7))*SROW
                             + (((lane >> 3) & 1) << 2))*4;

    float acc[4][4][4];
    #pragma unroll
    for (int a = 0; a < 4; a++)
        #pragma unroll
        for (int b = 0; b < 4; b++)
            #pragma unroll
            for (int c = 0; c < 4; c++) acc[a][b][c] = 0.f;

    CPAB(0, 0);
    CPAB(1, 32);

    const int NTILES = Hd/32;   // 16
    for (int kt = 0; kt < NTILES; kt++) {
        const int st = kt % NSTAGE;
        const uint32_t soff = (uint32_t)(st*STAGE_F)*4;
        if (kt + 1 < NTILES) asm volatile("cp.async.wait_group 1;" ::: "memory");
        else                 asm volatile("cp.async.wait_group 0;" ::: "memory");
        __syncthreads();
        #pragma unroll
        for (int ks = 0; ks < 4; ks++) {
            const uint32_t kb = soff + ks*32;
            // load both B fragments first (8 regs), then stream A one mt at a time
            uint32_t bf[2][4];
            ldm4(lb[0] + kb, bf[0]);
            ldm4(lb[1] + kb, bf[1]);
            #pragma unroll
            for (int mt = 0; mt < 4; mt++) {
                uint32_t af[4];
                ldm4(la[mt] + kb, af);
                af[0] = f2tf(__uint_as_float(af[0]));
                af[1] = f2tf(__uint_as_float(af[1]));
                af[2] = f2tf(__uint_as_float(af[2]));
                af[3] = f2tf(__uint_as_float(af[3]));
                #pragma unroll
                for (int nt = 0; nt < 4; nt++) {
                    const int ntp = nt >> 1, hb = (nt & 1) * 2;
                    asm volatile(
                        "mma.sync.aligned.m16n8k8.row.col.f32.tf32.tf32.f32 "
                        "{%0,%1,%2,%3}, {%4,%5,%6,%7}, {%8,%9}, {%0,%1,%2,%3};"
                        : "+f"(acc[mt][nt][0]), "+f"(acc[mt][nt][1]),
                          "+f"(acc[mt][nt][2]), "+f"(acc[mt][nt][3])
                        : "r"(af[0]), "r"(af[1]), "r"(af[2]), "r"(af[3]),
                          "r"(bf[ntp][hb]), "r"(bf[ntp][hb+1]));
                }
            }
        }
        if (kt + 2 < NTILES) CPAB((kt + 2) % NSTAGE, (kt + 2) * 32);
    }

    // -------- epilogue --------
    #pragma unroll
    for (int mt = 0; mt < 4; mt++) {
        #pragma unroll
        for (int hf = 0; hf < 2; hf++) {
            int r = row0 + wm*64 + mt*16 + g + hf*8;
            if (r >= M) continue;
            size_t co  = row_off(r, cmode, cshift);
            size_t a1o = add1 ? row_off(r, a1mode, a1shift) : 0;
            float sc = 1.f;
            if (smode) { float v = scale[r]; sc = (smode == 1) ? v : (1.f - v); }
            #pragma unroll
            for (int nt = 0; nt < 4; nt++) {
                int n = nb*128 + wn*32 + nt*8 + tig*2;
                float vx = acc[mt][nt][hf*2+0];
                float vy = acc[mt][nt][hf*2+1];
                if (smode) { vx *= sc; vy *= sc; }
                if (bias)  { vx += bias[n]; vy += bias[n+1]; }
                if (relu_flag) { vx = fmaxf(vx, 0.f); vy = fmaxf(vy, 0.f); }
                if (add1)  { vx += add1[a1o + n]; vy += add1[a1o + n + 1]; }
                if (add2)  { vx += add2[(size_t)r*Hd + n]; vy += add2[(size_t)r*Hd + n + 1]; }
                float2 o = make_float2(vx, vy);
                *(float2*)(C + co + n) = o;
            }
        }
    }
}

// -------- fused attention + aggregation + LN + ReLU, one block per (b,t) --------
// G padded to 2812 floats so S is 16B-aligned (S row stride 52 floats = 208B = 13*16)
#define GPAD 2812
#define ATTN_SMEM_FLOATS (53*512 + GPAD + 50*52 + 50 + 49 + 49 + 50 + 50 + 34)
#define ATTN_SMEM_BYTES  (ATTN_SMEM_FLOATS*4)

__global__ __launch_bounds__(512) void attn_agg_kernel(
    const float* __restrict__ X, const float* __restrict__ edge,
    const float* __restrict__ lng, const float* __restrict__ lnb,
    float* __restrict__ attn_out, float* __restrict__ spatial)
{
    extern __shared__ float sm[];
    float* Xs  = sm;
    float* G   = Xs + 53*512;
    float* S   = G + GPAD;
    float* qn  = S + 50*52;
    float* kn0 = qn + 50;
    float* kn1 = kn0 + 49;
    float* sAv = kn1 + 49;
    float* a49 = sAv + 50;
    float* red = a49 + 50;

    const int bt   = blockIdx.x;
    const int tid  = threadIdx.x;
    const int lane = tid & 31, warp = tid >> 5;

    float4* Xs4 = (float4*)Xs;
    const float4* xg = (const float4*)(X + (size_t)bt*NP*Hd);
    const float4* eg = (const float4*)edge;
    for (int u = tid; u < 53*128; u += 512) {
        int row = u >> 7;
        Xs4[u] = (row < NP) ? xg[u] : eg[u - NP*128];
    }
    __syncthreads();

    for (int p = warp; p < 1431; p += 16) {
        int i = (int)((sqrtf(8.0f*p + 1.0f) - 1.0f) * 0.5f);
        while ((i+1)*(i+2)/2 <= p) ++i;
        while (i*(i+1)/2 > p)     --i;
        int j = p - i*(i+1)/2;
        const float4* xi = Xs4 + i*128;
        const float4* xj = Xs4 + j*128;
        float a = 0.f;
        for (int u = lane; u < 128; u += 32) {
            float4 p1 = xi[u], p2 = xj[u];
            a += p1.x*p2.x + p1.y*p2.y + p1.z*p2.z + p1.w*p2.w;
        }
        #pragma unroll
        for (int o = 16; o; o >>= 1) a += __shfl_xor_sync(0xffffffffu, a, o);
        if (lane == 0) { G[i*53+j] = a; G[j*53+i] = a; }
    }
    __syncthreads();

    if (tid < 50) qn[tid] = fmaxf(sqrtf(G[tid*53+tid]), 1e-12f);
    if (tid >= 64 && tid < 64+49) {
        int j = tid - 64;
        kn0[j] = fmaxf(sqrtf(G[j*53+j] + 2.f*G[j*53+50] + G[50*53+50]), 1e-12f);
    }
    if (tid >= 128 && tid < 128+49) {
        int j = tid - 128;
        kn1[j] = fmaxf(sqrtf(G[j*53+j] + 2.f*G[j*53+51] + G[51*53+51]), 1e-12f);
    }
    if (tid == 192)
        red[33] = fmaxf(sqrtf(G[49*53+49] + 2.f*G[49*53+52] + G[52*53+52]), 1e-12f);
    __syncthreads();
    const float kn2 = red[33];

    for (int p = tid; p < 2500; p += 512) {
        int i = p / 50, j = p - (p/50)*50;
        float v;
        if (i == j)       v = NEGV;
        else if (j == 49) v = (G[i*53+49] + G[i*53+52]) / (qn[i]*kn2);
        else if (i == 49) v = (G[49*53+j] + G[49*53+51]) / (qn[49]*kn1[j]);
        else {
            int qr = i/7, qc = i - (i/7)*7, kr = j/7, kc = j - (j/7)*7;
            int r0 = (qr-1 > 0) ? qr-1 : 0;
            int c0 = qc-1; c0 = (c0 < 0) ? 0 : ((c0 > 4) ? 4 : c0);
            bool ok = (kr >= r0 && kr <= r0+2 && kc >= c0 && kc <= c0+2);
            v = ok ? (G[i*53+j] + G[i*53+50]) / (qn[i]*kn0[j]) : NEGV;
        }
        S[i*52+j] = v;
    }
    __syncthreads();

    for (int i = warp; i < 50; i += 16) {
        float v0 = S[i*52 + lane];
        int j1 = lane + 32;
        float v1 = (j1 < 50) ? S[i*52 + j1] : -3.4e38f;
        float m = fmaxf(v0, v1);
        #pragma unroll
        for (int o = 16; o; o >>= 1) m = fmaxf(m, __shfl_xor_sync(0xffffffffu, m, o));
        float e0 = expf(v0 - m);
        float e1 = (j1 < 50) ? expf(v1 - m) : 0.f;
        float s = e0 + e1;
        #pragma unroll
        for (int o = 16; o; o >>= 1) s += __shfl_xor_sync(0xffffffffu, s, o);
        float e49 = __shfl_sync(0xffffffffu, e1, 17);
        float inv = 1.f / s;
        float p0 = e0 * inv, p1 = e1 * inv;
        S[i*52 + lane] = p0;
        if (j1 < 50) S[i*52 + j1] = p1;
        if (lane == 0) { sAv[i] = (s - e49)*inv; a49[i] = e49*inv; }
        if (attn_out) {
            attn_out[((size_t)bt*50 + i)*50 + lane] = p0;
            if (j1 < 50) attn_out[((size_t)bt*50 + i)*50 + j1] = p1;
        }
    }
    __syncthreads();

    // aggregation: thread owns feature h; j blocked by 4 with float4 S loads
    const int h = tid;
    float accv[50];
    #pragma unroll
    for (int i = 0; i < 50; i++) accv[i] = Xs[i*512 + h];
    #pragma unroll 4
    for (int j0 = 0; j0 < 48; j0 += 4) {
        float x0 = Xs[(j0+0)*512 + h];
        float x1 = Xs[(j0+1)*512 + h];
        float x2 = Xs[(j0+2)*512 + h];
        float x3 = Xs[(j0+3)*512 + h];
        #pragma unroll
        for (int i = 0; i < 50; i++) {
            float4 s = *(const float4*)&S[i*52 + j0];
            accv[i] += s.x*x0 + s.y*x1 + s.z*x2 + s.w*x3;
        }
    }
    {
        float x0 = Xs[48*512 + h];
        float x1 = Xs[49*512 + h];
        #pragma unroll
        for (int i = 0; i < 50; i++) {
            float2 s = *(const float2*)&S[i*52 + 48];
            accv[i] += s.x*x0 + s.y*x1;
        }
    }
    const float e0v = Xs[50*512 + h], e1v = Xs[51*512 + h], e2v = Xs[52*512 + h];
    #pragma unroll
    for (int i = 0; i < 50; i++)
        accv[i] += sAv[i]*((i == 49) ? e1v : e0v) + a49[i]*e2v;

    __syncthreads();   // all reads of Xs rows 0..49 and S done
    #pragma unroll
    for (int i = 0; i < 50; i++) Xs[i*512 + h] = accv[i];
    S[tid]       = lng[tid];
    S[512 + tid] = lnb[tid];
    __syncthreads();

    // per-warp LayerNorm+ReLU rows
    for (int i = warp; i < 50; i += 16) {
        float s1 = 0.f, s2 = 0.f;
        #pragma unroll
        for (int k = 0; k < 16; k++) {
            float v = Xs[i*512 + lane + k*32];
            s1 += v; s2 += v*v;
        }
        #pragma unroll
        for (int o = 16; o; o >>= 1) {
            s1 += __shfl_xor_sync(0xffffffffu, s1, o);
            s2 += __shfl_xor_sync(0xffffffffu, s2, o);
        }
        float mn = s1 * (1.f/512.f);
        float rs = rsqrtf(s2*(1.f/512.f) - mn*mn + 1e-5f);
        float* dst = spatial + ((size_t)bt*NP + i)*Hd;
        #pragma unroll
        for (int k = 0; k < 16; k++) {
            int u = lane + k*32;
            float v = Xs[i*512 + u];
            dst[u] = fmaxf(0.f, (v - mn)*rs*S[u] + S[512 + u]);
        }
    }
}

// -------- cosine between spatial[t] and spatial[t-1] --------
__global__ void cos_kernel(const float* __restrict__ sp,
                           float* __restrict__ c1, float* __restrict__ c2) {
    int gw = (int)((blockIdx.x*(size_t)blockDim.x + threadIdx.x) >> 5);
    int lane = threadIdx.x & 31;
    if (gw >= M_T) return;
    int b   = gw / ((Tt-1)*NP);
    int rem = gw - b*(Tt-1)*NP;
    int tt  = rem / NP;
    int i   = rem - tt*NP;
    const float4* pa = (const float4*)(sp + (((size_t)(b*Tt + tt + 1))*NP + i)*Hd);
    const float4* pb = (const float4*)(sp + (((size_t)(b*Tt + tt))*NP + i)*Hd);
    float d = 0.f, na = 0.f, nb2 = 0.f;
    for (int u = lane; u < 128; u += 32) {
        float4 a = pa[u], c = pb[u];
        d   += a.x*c.x + a.y*c.y + a.z*c.z + a.w*c.w;
        na  += a.x*a.x + a.y*a.y + a.z*a.z + a.w*a.w;
        nb2 += c.x*c.x + c.y*c.y + c.z*c.z + c.w*c.w;
    }
    #pragma unroll
    for (int o = 16; o; o >>= 1) {
        d   += __shfl_xor_sync(0xffffffffu, d, o);
        na  += __shfl_xor_sync(0xffffffffu, na, o);
        nb2 += __shfl_xor_sync(0xffffffffu, nb2, o);
    }
    if (lane == 0) {
        float v = d / (fmaxf(sqrtf(na), 1e-8f) * fmaxf(sqrtf(nb2), 1e-8f));
        c1[gw] = v;
        if (c2) c2[gw] = v;
    }
}

// -------- copy t=0 rows of spatial into z --------
__global__ void copy_t0(const float* __restrict__ sp, float* __restrict__ z) {
    int u = blockIdx.x*blockDim.x + threadIdx.x;
    if (u >= Bsz*NP*(Hd/4)) return;
    int h4 = u & 127;
    int rem = u >> 7;
    int i = rem % NP;
    int b = rem / NP;
    size_t off = ((size_t)(b*Tt)*NP + i)*(Hd/4) + h4;
    ((float4*)z)[off] = ((const float4*)sp)[off];
}

// -------- LayerNorm rows of 512, block per row --------
__global__ __launch_bounds__(512) void ln512(const float* __restrict__ X,
                                             const float* __restrict__ g,
                                             const float* __restrict__ b,
                                             float* __restrict__ Y) {
    __shared__ float red[34];
    size_t base = (size_t)blockIdx.x * Hd;
    int tid = threadIdx.x, lane = tid & 31, warp = tid >> 5;
    float v = X[base + tid];
    float s1 = v, s2 = v*v;
    #pragma unroll
    for (int o = 16; o; o >>= 1) {
        s1 += __shfl_xor_sync(0xffffffffu, s1, o);
        s2 += __shfl_xor_sync(0xffffffffu, s2, o);
    }
    if (!lane) { red[warp] = s1; red[16+warp] = s2; }
    __syncthreads();
    if (warp == 0) {
        float a = (lane < 16) ? red[lane]    : 0.f;
        float c = (lane < 16) ? red[16+lane] : 0.f;
        #pragma unroll
        for (int o = 8; o; o >>= 1) {
            a += __shfl_xor_sync(0xffffffffu, a, o);
            c += __shfl_xor_sync(0xffffffffu, c, o);
        }
        if (!lane) {
            float m = a * (1.f/512.f);
            red[32] = m;
            red[33] = rsqrtf(c*(1.f/512.f) - m*m + 1e-5f);
        }
    }
    __syncthreads();
    Y[base + tid] = (v - red[32])*red[33]*g[tid] + b[tid];
}

extern "C" void kernel_launch(void* const* d_in, const int* in_sizes, int n_in,
                              void* d_out, int out_size) {
    (void)in_sizes; (void)n_in; (void)out_size;
    const float* vis   = (const float*)d_in[0];
    const float* aud   = (const float*)d_in[1];
    const float* in_W  = (const float*)d_in[2];
    const float* in_b  = (const float*)d_in[3];
    const float* out_W = (const float*)d_in[4];
    const float* out_b = (const float*)d_in[5];

    float* out      = (float*)d_out;
    float* attn_out = out + (size_t)M_ALL*Hd;
    float* cos_out  = attn_out + (size_t)BT*NP*NP;

    float *gx, *gsp, *gz, *gtmp, *gcos, *gwr;
    cudaGetSymbolAddress((void**)&gx,   g_x);
    cudaGetSymbolAddress((void**)&gsp,  g_sp);
    cudaGetSymbolAddress((void**)&gz,   g_z);
    cudaGetSymbolAddress((void**)&gtmp, g_tmp);
    cudaGetSymbolAddress((void**)&gcos, g_cos);
    cudaGetSymbolAddress((void**)&gwr,  g_wr);

    cudaFuncSetAttribute(attn_agg_kernel,
                         cudaFuncAttributeMaxDynamicSharedMemorySize, ATTN_SMEM_BYTES);
    cudaFuncSetAttribute(gemm_tc,
                         cudaFuncAttributeMaxDynamicSharedMemorySize, GT_SMEM);

    // pre-round the 8 weight matrices to tf32 (RN), one launch
    WPtrs wp;
    wp.p[0] = in_W;  wp.p[1] = out_W;
    wp.p[2] = (const float*)d_in[9];  wp.p[3] = (const float*)d_in[11];
    wp.p[4] = (const float*)d_in[13]; wp.p[5] = (const float*)d_in[17];
    wp.p[6] = (const float*)d_in[19]; wp.p[7] = (const float*)d_in[21];
    round_tf32_k<<<8192, 256>>>(wp, gwr);
    const float* W_in  = gwr + 0*512*512;
    const float* W_out = gwr + (size_t)1*512*512;
    const float* W_l[2][3] = { { gwr+(size_t)2*512*512, gwr+(size_t)3*512*512, gwr+(size_t)4*512*512 },
                               { gwr+(size_t)5*512*512, gwr+(size_t)6*512*512, gwr+(size_t)7*512*512 } };

    // input projection
    concat_kernel<<<(M_ALL*128 + 255)/256, 256>>>(vis, aud, gz);
    dim3 gAll(4, (M_ALL + 127)/128);
    gemm_tc<<<gAll, 256, GT_SMEM>>>(gz, 0, 0, nullptr, 0, W_in, in_b, 0,
                                    nullptr, 0, 0, nullptr, gx, 0, 0, M_ALL);

    for (int L = 0; L < 2; L++) {
        const float* edge = (const float*)d_in[6 + L*8];
        const float* lng  = (const float*)d_in[7 + L*8];
        const float* lnb  = (const float*)d_in[8 + L*8];
        const float* bc   = (const float*)d_in[10 + L*8];
        const float* bs   = (const float*)d_in[12 + L*8];

        attn_agg_kernel<<<BT, 512, ATTN_SMEM_BYTES>>>(
            gx, edge, lng, lnb, (L == 1) ? attn_out : nullptr, gsp);

        cos_kernel<<<(M_T*32 + 255)/256, 256>>>(gsp, gcos, (L == 1) ? cos_out : nullptr);

        dim3 gT(4, (M_T + 127)/128);
        // tc = relu(cos * (prev @ Wc^T) + bc) -> gtmp (dense rows)
        gemm_tc<<<gT, 256, GT_SMEM>>>(gsp, 1, 0, gcos, 1, W_l[L][0], bc, 1,
                                      nullptr, 0, 0, nullptr, gtmp, 0, 0, M_T);
        // z[t+1] = cur + tc + relu((1-cos) * (cur @ Ws^T) + bs)
        gemm_tc<<<gT, 256, GT_SMEM>>>(gsp, 1, 1, gcos, 2, W_l[L][1], bs, 1,
                                      gsp, 1, 1, gtmp, gz, 1, 1, M_T);
        copy_t0<<<(Bsz*NP*128 + 255)/256, 256>>>(gsp, gz);

        ln512<<<M_ALL, 512>>>(gz, lng, lnb, gtmp);
        // x = x + relu(LN(z) @ Wo^T)
        gemm_tc<<<gAll, 256, GT_SMEM>>>(gtmp, 0, 0, nullptr, 0, W_l[L][2], nullptr, 1,
                                        gx, 0, 0, nullptr, gx, 0, 0, M_ALL);
    }

    // output projection
    gemm_tc<<<gAll, 256, GT_SMEM>>>(gx, 0, 0, nullptr, 0, W_out, out_b, 0,
                                    nullptr, 0, 0, nullptr, out, 0, 0, M_ALL);
}

// round 9
// speedup vs baseline: 3.6712x; 1.6330x over previous
#include <cuda_runtime.h>
#include <cuda_fp16.h>
#include <math.h>
#include <cstdint>

#define Bsz 16
#define Tt 64
#define NV 49
#define NP 50
#define Hd 512
#define BT (Bsz*Tt)              // 1024
#define M_ALL (BT*NP)            // 51200
#define M_T (Bsz*(Tt-1)*NP)      // 50400
#define NEGV (-1000000000.0f)

// -------- static device scratch (no allocations allowed) --------
__device__ float g_x[(size_t)M_ALL*Hd];
__device__ float g_sp[(size_t)M_ALL*Hd];
__device__ float g_z[(size_t)M_ALL*Hd];
__device__ float g_tmp[(size_t)M_ALL*Hd];
__device__ float g_cos[M_T];
__device__ __half g_xh[(size_t)M_ALL*Hd];
__device__ __half g_sph[(size_t)M_ALL*Hd];
__device__ __half g_zh[(size_t)M_ALL*Hd];
__device__ __half g_tmph[(size_t)M_ALL*Hd];
__device__ __half g_wh[8][512*512];   // fp16-rounded weights

__device__ __forceinline__ size_t row_off(int r, int mode, int shift) {
    if (mode == 0) return (size_t)r * Hd;
    int b   = r / ((Tt-1)*NP);
    int rem = r - b*(Tt-1)*NP;
    int tt  = rem / NP;
    int i   = rem - tt*NP;
    return ((size_t)((b*Tt + tt + shift)*NP) + i) * Hd;
}

__device__ __forceinline__ uint32_t f2tf(float f) {
    uint32_t r; asm("cvt.rna.tf32.f32 %0, %1;" : "=r"(r) : "f"(f)); return r;
}
__device__ __forceinline__ void cpa16(uint32_t dst, const void* src) {
    asm volatile("cp.async.cg.shared.global [%0], [%1], 16;" :: "r"(dst), "l"(src));
}
__device__ __forceinline__ uint32_t smem_u32(const void* p) {
    uint32_t a;
    asm("{ .reg .u64 t; cvta.to.shared.u64 t, %1; cvt.u32.u64 %0, t; }" : "=r"(a) : "l"(p));
    return a;
}
__device__ __forceinline__ void ldm4(uint32_t addr, uint32_t* r) {
    asm volatile("ldmatrix.sync.aligned.m8n8.x4.shared.b16 {%0,%1,%2,%3}, [%4];"
                 : "=r"(r[0]), "=r"(r[1]), "=r"(r[2]), "=r"(r[3]) : "r"(addr));
}

// -------- round all 8 f32 weight matrices to fp16 (RN), one launch --------
struct WPtrs { const float* p[8]; };
__global__ void round_h_k(WPtrs w, __half* __restrict__ out) {
    size_t i = (size_t)blockIdx.x * blockDim.x + threadIdx.x;   // < 8*262144
    int m = (int)(i >> 18);
    int e = (int)(i & 0x3FFFF);
    out[i] = __float2half_rn(w.p[m][e]);
}

// -------- concat(visual, audio) -> dense [BT*NP, H] + half copy --------
__global__ void concat_kernel(const float* __restrict__ vis,
                              const float* __restrict__ aud,
                              float* __restrict__ out,
                              __half* __restrict__ outh) {
    size_t idx = (size_t)blockIdx.x * blockDim.x + threadIdx.x;
    size_t total = (size_t)M_ALL * (Hd/4);
    if (idx >= total) return;
    int h4 = (int)(idx & 127);
    size_t row = idx >> 7;
    int i = (int)(row % NP);
    size_t bt = row / NP;
    float4 v;
    if (i < NV) v = ((const float4*)vis)[(bt*NV + i)*(Hd/4) + h4];
    else        v = ((const float4*)aud)[bt*(Hd/4) + h4];
    ((float4*)out)[idx] = v;
    __half2 h0 = __floats2half2_rn(v.x, v.y);
    __half2 h1 = __floats2half2_rn(v.z, v.w);
    __half2* oh = (__half2*)(outh + idx*4);
    oh[0] = h0; oh[1] = h1;
}

// ============ fp16 mma.sync GEMM, K-chunk 64, 3-stage cp.async ============
#define SROWH 72                  // halves per smem row (64 data + 8 pad)
#define ASTG_B (128*SROWH*2)      // 18432 bytes per stage per matrix
#define NSTAGE 3
#define GH_SMEM (2*NSTAGE*ASTG_B) // 110592 bytes

__global__ void __launch_bounds__(256, 2) gemm_fp16(
    const __half* __restrict__ A, int amode, int ashift,
    const float* __restrict__ scale, int smode,      // 0 none, 1 s, 2 (1-s)
    const __half* __restrict__ W,                    // fp16 [512,512] k-major
    const float* __restrict__ bias, int relu_flag,
    const float* __restrict__ add1, int a1mode, int a1shift,
    const float* __restrict__ add2,                  // dense row index
    float* __restrict__ C, __half* __restrict__ Ch,
    int cmode, int cshift, int M)
{
    extern __shared__ char smraw[];
    const uint32_t sm0 = smem_u32(smraw);
    const int tid  = threadIdx.x;
    const int wid  = tid >> 5;
    const int lane = tid & 31;
    const int tig  = lane & 3;
    const int wm   = wid & 1;        // 2 warps in m (64 rows each)
    const int wn   = wid >> 1;       // 4 warps in n (32 cols each)
    const int nb   = blockIdx.x;     // 0..3
    const int row0 = blockIdx.y * 128;
    const int g    = lane >> 2;

    // global->smem: thread -> row (tid>>1), half-chunk (tid&1) of 64 halves
    const int ar = tid >> 1, ah = tid & 1;
    int gra = row0 + ar; if (gra >= M) gra = M - 1;
    const __half* aptr = A + row_off(gra, amode, ashift) + ah*32;
    const __half* bptr = W + (size_t)(nb*128 + ar)*Hd + ah*32;
    const uint32_t sa_addr = sm0 + (uint32_t)(ar*SROWH + ah*32)*2;
    const uint32_t sb_addr = sm0 + (uint32_t)(NSTAGE*128*SROWH + ar*SROWH + ah*32)*2;

    auto CPAB = [&](int st, int k0) {   // k0 in halves
        uint32_t so = (uint32_t)st * ASTG_B;
        #pragma unroll
        for (int j = 0; j < 4; j++)
            cpa16(sa_addr + so + j*16, aptr + k0 + j*8);
        #pragma unroll
        for (int j = 0; j < 4; j++)
            cpa16(sb_addr + so + j*16, bptr + k0 + j*8);
        asm volatile("cp.async.commit_group;" ::: "memory");
    };

    // ldmatrix lane addresses (bytes, stage-relative)
    uint32_t la[4], lb[2];
    #pragma unroll
    for (int mt = 0; mt < 4; mt++)
        la[mt] = sm0 + (uint32_t)((wm*64 + mt*16 + (lane & 15))*SROWH + (lane >> 4)*8)*2;
    #pragma unroll
    for (int ntp = 0; ntp < 2; ntp++)
        lb[ntp] = sm0 + (uint32_t)(NSTAGE*128*SROWH)*2
                + (uint32_t)((wn*32 + ntp*16 + (lane & 15))*SROWH + (lane >> 4)*8)*2;

    float acc[4][4][4];
    #pragma unroll
    for (int a = 0; a < 4; a++)
        #pragma unroll
        for (int b = 0; b < 4; b++)
            #pragma unroll
            for (int c = 0; c < 4; c++) acc[a][b][c] = 0.f;

    CPAB(0, 0);
    CPAB(1, 64);

    const int NTILES = Hd/64;   // 8
    for (int kt = 0; kt < NTILES; kt++) {
        const int st = kt % NSTAGE;
        const uint32_t soff = (uint32_t)st * ASTG_B;
        if (kt + 1 < NTILES) asm volatile("cp.async.wait_group 1;" ::: "memory");
        else                 asm volatile("cp.async.wait_group 0;" ::: "memory");
        __syncthreads();
        #pragma unroll
        for (int ks = 0; ks < 4; ks++) {
            const uint32_t kb = soff + ks*32;    // k16 = 32 bytes
            uint32_t bf0[4], bf1[4];
            ldm4(lb[0] + kb, bf0);
            ldm4(lb[1] + kb, bf1);
            #pragma unroll
            for (int mt = 0; mt < 4; mt++) {
                uint32_t af[4];
                ldm4(la[mt] + kb, af);
                #pragma unroll
                for (int nt = 0; nt < 4; nt++) {
                    const uint32_t* bp = (nt & 2) ? bf1 : bf0;
                    const int sel = nt & 1;
                    asm volatile(
                        "mma.sync.aligned.m16n8k16.row.col.f32.f16.f16.f32 "
                        "{%0,%1,%2,%3}, {%4,%5,%6,%7}, {%8,%9}, {%0,%1,%2,%3};"
                        : "+f"(acc[mt][nt][0]), "+f"(acc[mt][nt][1]),
                          "+f"(acc[mt][nt][2]), "+f"(acc[mt][nt][3])
                        : "r"(af[0]), "r"(af[1]), "r"(af[2]), "r"(af[3]),
                          "r"(bp[sel]), "r"(bp[sel+2]));
                }
            }
        }
        if (kt + 2 < NTILES) CPAB((kt + 2) % NSTAGE, (kt + 2) * 64);
    }

    // -------- epilogue --------
    #pragma unroll
    for (int mt = 0; mt < 4; mt++) {
        #pragma unroll
        for (int hf = 0; hf < 2; hf++) {
            int r = row0 + wm*64 + mt*16 + g + hf*8;
            if (r >= M) continue;
            size_t co  = row_off(r, cmode, cshift);
            size_t a1o = add1 ? row_off(r, a1mode, a1shift) : 0;
            float sc = 1.f;
            if (smode) { float v = scale[r]; sc = (smode == 1) ? v : (1.f - v); }
            #pragma unroll
            for (int nt = 0; nt < 4; nt++) {
                int n = nb*128 + wn*32 + nt*8 + tig*2;
                float vx = acc[mt][nt][hf*2+0];
                float vy = acc[mt][nt][hf*2+1];
                if (smode) { vx *= sc; vy *= sc; }
                if (bias)  { vx += bias[n]; vy += bias[n+1]; }
                if (relu_flag) { vx = fmaxf(vx, 0.f); vy = fmaxf(vy, 0.f); }
                if (add1)  { vx += add1[a1o + n]; vy += add1[a1o + n + 1]; }
                if (add2)  { vx += add2[(size_t)r*Hd + n]; vy += add2[(size_t)r*Hd + n + 1]; }
                *(float2*)(C + co + n) = make_float2(vx, vy);
                if (Ch) *(__half2*)(Ch + co + n) = __floats2half2_rn(vx, vy);
            }
        }
    }
}

// -------- fused attention (tf32-mma Gram) + agg + LN + ReLU, block per (b,t) ----
#define XROW 516                           // floats per padded Xs row
#define GSTR 66
#define ATTN_SMEM_FLOATS (64*XROW + 64*GSTR + 50*52 + 50 + 49 + 49 + 50 + 50 + 34)
#define ATTN_SMEM_BYTES  (ATTN_SMEM_FLOATS*4)

__global__ __launch_bounds__(512) void attn_agg_kernel(
    const float* __restrict__ X, const float* __restrict__ edge,
    const float* __restrict__ lng, const float* __restrict__ lnb,
    float* __restrict__ attn_out, float* __restrict__ spatial,
    __half* __restrict__ spatial_h)
{
    extern __shared__ float sm[];
    float* Xs  = sm;                  // 64 x 516
    float* G   = Xs + 64*XROW;        // 64 x 66
    float* S   = G + 64*GSTR;         // 50 x 52  (16B-aligned)
    float* qn  = S + 50*52;
    float* kn0 = qn + 50;
    float* kn1 = kn0 + 49;
    float* sAv = kn1 + 49;
    float* a49 = sAv + 50;
    float* red = a49 + 50;

    const int bt   = blockIdx.x;
    const int tid  = threadIdx.x;
    const int lane = tid & 31, warp = tid >> 5;

    // load 64 padded rows: 0-49 = x, 50-52 = edge, 53-63 = zero
    {
        const float4* xg = (const float4*)(X + (size_t)bt*NP*Hd);
        const float4* eg = (const float4*)edge;
        for (int u = tid; u < 64*128; u += 512) {
            int row = u >> 7, c4 = u & 127;
            float4 v;
            if (row < NP)      v = xg[row*128 + c4];
            else if (row < 53) v = eg[(row - NP)*128 + c4];
            else               v = make_float4(0.f, 0.f, 0.f, 0.f);
            *(float4*)&Xs[row*XROW + c4*4] = v;
        }
    }
    __syncthreads();

    // ---- Gram via tf32 mma: G[64x64] = Xs @ Xs^T ----
    // 16 warps, each computes one 16x16 tile: wm = warp&3 (rows), wn = warp>>2 (cols)
    {
        const uint32_t xs0 = smem_u32(Xs);
        const int wm = warp & 3, wn = warp >> 2;
        uint32_t ga = xs0 + (uint32_t)((wm*16 + (lane & 15))*XROW + (lane >> 4)*4)*4;
        uint32_t gb = xs0 + (uint32_t)((wn*16 + ((lane & 16) >> 1) + (lane & 7))*XROW
                                       + (((lane >> 3) & 1))*4)*4;
        float gacc[2][4];
        #pragma unroll
        for (int a = 0; a < 2; a++)
            #pragma unroll
            for (int b = 0; b < 4; b++) gacc[a][b] = 0.f;
        for (int kk = 0; kk < 64; kk++) {
            const uint32_t kb = kk*32;     // k8 = 32 bytes
            uint32_t af[4], bf[4];
            ldm4(ga + kb, af);
            ldm4(gb + kb, bf);
            #pragma unroll
            for (int q = 0; q < 4; q++) {
                af[q] = f2tf(__uint_as_float(af[q]));
                bf[q] = f2tf(__uint_as_float(bf[q]));
            }
            #pragma unroll
            for (int nt = 0; nt < 2; nt++) {
                asm volatile(
                    "mma.sync.aligned.m16n8k8.row.col.f32.tf32.tf32.f32 "
                    "{%0,%1,%2,%3}, {%4,%5,%6,%7}, {%8,%9}, {%0,%1,%2,%3};"
                    : "+f"(gacc[nt][0]), "+f"(gacc[nt][1]),
                      "+f"(gacc[nt][2]), "+f"(gacc[nt][3])
                    : "r"(af[0]), "r"(af[1]), "r"(af[2]), "r"(af[3]),
                      "r"(bf[nt*2]), "r"(bf[nt*2+1]));
            }
        }
        #pragma unroll
        for (int nt = 0; nt < 2; nt++) {
            int gr = wm*16 + (lane >> 2);
            int gc = wn*16 + nt*8 + (lane & 3)*2;
            *(float2*)&G[gr*GSTR + gc]     = make_float2(gacc[nt][0], gacc[nt][1]);
            *(float2*)&G[(gr+8)*GSTR + gc] = make_float2(gacc[nt][2], gacc[nt][3]);
        }
    }
    __syncthreads();

    if (tid < 50) qn[tid] = fmaxf(sqrtf(G[tid*GSTR+tid]), 1e-12f);
    if (tid >= 64 && tid < 64+49) {
        int j = tid - 64;
        kn0[j] = fmaxf(sqrtf(G[j*GSTR+j] + 2.f*G[j*GSTR+50] + G[50*GSTR+50]), 1e-12f);
    }
    if (tid >= 128 && tid < 128+49) {
        int j = tid - 128;
        kn1[j] = fmaxf(sqrtf(G[j*GSTR+j] + 2.f*G[j*GSTR+51] + G[51*GSTR+51]), 1e-12f);
    }
    if (tid == 192)
        red[33] = fmaxf(sqrtf(G[49*GSTR+49] + 2.f*G[49*GSTR+52] + G[52*GSTR+52]), 1e-12f);
    __syncthreads();
    const float kn2 = red[33];

    for (int p = tid; p < 2500; p += 512) {
        int i = p / 50, j = p - (p/50)*50;
        float v;
        if (i == j)       v = NEGV;
        else if (j == 49) v = (G[i*GSTR+49] + G[i*GSTR+52]) / (qn[i]*kn2);
        else if (i == 49) v = (G[49*GSTR+j] + G[49*GSTR+51]) / (qn[49]*kn1[j]);
        else {
            int qr = i/7, qc = i - (i/7)*7, kr = j/7, kc = j - (j/7)*7;
            int r0 = (qr-1 > 0) ? qr-1 : 0;
            int c0 = qc-1; c0 = (c0 < 0) ? 0 : ((c0 > 4) ? 4 : c0);
            bool ok = (kr >= r0 && kr <= r0+2 && kc >= c0 && kc <= c0+2);
            v = ok ? (G[i*GSTR+j] + G[i*GSTR+50]) / (qn[i]*kn0[j]) : NEGV;
        }
        S[i*52+j] = v;
    }
    __syncthreads();

    for (int i = warp; i < 50; i += 16) {
        float v0 = S[i*52 + lane];
        int j1 = lane + 32;
        float v1 = (j1 < 50) ? S[i*52 + j1] : -3.4e38f;
        float m = fmaxf(v0, v1);
        #pragma unroll
        for (int o = 16; o; o >>= 1) m = fmaxf(m, __shfl_xor_sync(0xffffffffu, m, o));
        float e0 = expf(v0 - m);
        float e1 = (j1 < 50) ? expf(v1 - m) : 0.f;
        float s = e0 + e1;
        #pragma unroll
        for (int o = 16; o; o >>= 1) s += __shfl_xor_sync(0xffffffffu, s, o);
        float e49 = __shfl_sync(0xffffffffu, e1, 17);
        float inv = 1.f / s;
        float p0 = e0 * inv, p1 = e1 * inv;
        S[i*52 + lane] = p0;
        if (j1 < 50) S[i*52 + j1] = p1;
        if (lane == 0) { sAv[i] = (s - e49)*inv; a49[i] = e49*inv; }
        if (attn_out) {
            attn_out[((size_t)bt*50 + i)*50 + lane] = p0;
            if (j1 < 50) attn_out[((size_t)bt*50 + i)*50 + j1] = p1;
        }
    }
    __syncthreads();

    // aggregation: thread owns feature h; j blocked by 4 with float4 S loads
    const int h = tid;
    float accv[50];
    #pragma unroll
    for (int i = 0; i < 50; i++) accv[i] = Xs[i*XROW + h];
    #pragma unroll 4
    for (int j0 = 0; j0 < 48; j0 += 4) {
        float x0 = Xs[(j0+0)*XROW + h];
        float x1 = Xs[(j0+1)*XROW + h];
        float x2 = Xs[(j0+2)*XROW + h];
        float x3 = Xs[(j0+3)*XROW + h];
        #pragma unroll
        for (int i = 0; i < 50; i++) {
            float4 s = *(const float4*)&S[i*52 + j0];
            accv[i] += s.x*x0 + s.y*x1 + s.z*x2 + s.w*x3;
        }
    }
    {
        float x0 = Xs[48*XROW + h];
        float x1 = Xs[49*XROW + h];
        #pragma unroll
        for (int i = 0; i < 50; i++) {
            float2 s = *(const float2*)&S[i*52 + 48];
            accv[i] += s.x*x0 + s.y*x1;
        }
    }
    const float e0v = Xs[50*XROW + h], e1v = Xs[51*XROW + h], e2v = Xs[52*XROW + h];
    #pragma unroll
    for (int i = 0; i < 50; i++)
        accv[i] += sAv[i]*((i == 49) ? e1v : e0v) + a49[i]*e2v;

    __syncthreads();
    #pragma unroll
    for (int i = 0; i < 50; i++) Xs[i*XROW + h] = accv[i];
    S[tid]       = lng[tid];
    S[512 + tid] = lnb[tid];
    __syncthreads();

    for (int i = warp; i < 50; i += 16) {
        float s1 = 0.f, s2 = 0.f;
        #pragma unroll
        for (int k = 0; k < 16; k++) {
            float v = Xs[i*XROW + lane + k*32];
            s1 += v; s2 += v*v;
        }
        #pragma unroll
        for (int o = 16; o; o >>= 1) {
            s1 += __shfl_xor_sync(0xffffffffu, s1, o);
            s2 += __shfl_xor_sync(0xffffffffu, s2, o);
        }
        float mn = s1 * (1.f/512.f);
        float rs = rsqrtf(s2*(1.f/512.f) - mn*mn + 1e-5f);
        float*  dst  = spatial   + ((size_t)bt*NP + i)*Hd;
        __half* dsth = spatial_h + ((size_t)bt*NP + i)*Hd;
        #pragma unroll
        for (int k = 0; k < 16; k++) {
            int u = lane + k*32;
            float v = Xs[i*XROW + u];
            float o = fmaxf(0.f, (v - mn)*rs*S[u] + S[512 + u]);
            dst[u]  = o;
            dsth[u] = __float2half_rn(o);
        }
    }
}

// -------- cosine between spatial[t] and spatial[t-1] --------
__global__ void cos_kernel(const float* __restrict__ sp,
                           float* __restrict__ c1, float* __restrict__ c2) {
    int gw = (int)((blockIdx.x*(size_t)blockDim.x + threadIdx.x) >> 5);
    int lane = threadIdx.x & 31;
    if (gw >= M_T) return;
    int b   = gw / ((Tt-1)*NP);
    int rem = gw - b*(Tt-1)*NP;
    int tt  = rem / NP;
    int i   = rem - tt*NP;
    const float4* pa = (const float4*)(sp + (((size_t)(b*Tt + tt + 1))*NP + i)*Hd);
    const float4* pb = (const float4*)(sp + (((size_t)(b*Tt + tt))*NP + i)*Hd);
    float d = 0.f, na = 0.f, nb2 = 0.f;
    for (int u = lane; u < 128; u += 32) {
        float4 a = pa[u], c = pb[u];
        d   += a.x*c.x + a.y*c.y + a.z*c.z + a.w*c.w;
        na  += a.x*a.x + a.y*a.y + a.z*a.z + a.w*a.w;
        nb2 += c.x*c.x + c.y*c.y + c.z*c.z + c.w*c.w;
    }
    #pragma unroll
    for (int o = 16; o; o >>= 1) {
        d   += __shfl_xor_sync(0xffffffffu, d, o);
        na  += __shfl_xor_sync(0xffffffffu, na, o);
        nb2 += __shfl_xor_sync(0xffffffffu, nb2, o);
    }
    if (lane == 0) {
        float v = d / (fmaxf(sqrtf(na), 1e-8f) * fmaxf(sqrtf(nb2), 1e-8f));
        c1[gw] = v;
        if (c2) c2[gw] = v;
    }
}

// -------- copy t=0 rows of spatial into z --------
__global__ void copy_t0(const float* __restrict__ sp, float* __restrict__ z) {
    int u = blockIdx.x*blockDim.x + threadIdx.x;
    if (u >= Bsz*NP*(Hd/4)) return;
    int h4 = u & 127;
    int rem = u >> 7;
    int i = rem % NP;
    int b = rem / NP;
    size_t off = ((size_t)(b*Tt)*NP + i)*(Hd/4) + h4;
    ((float4*)z)[off] = ((const float4*)sp)[off];
}

// -------- LayerNorm rows of 512, block per row, dual fp32+fp16 out --------
__global__ __launch_bounds__(512) void ln512(const float* __restrict__ X,
                                             const float* __restrict__ g,
                                             const float* __restrict__ b,
                                             float* __restrict__ Y,
                                             __half* __restrict__ Yh) {
    __shared__ float red[34];
    size_t base = (size_t)blockIdx.x * Hd;
    int tid = threadIdx.x, lane = tid & 31, warp = tid >> 5;
    float v = X[base + tid];
    float s1 = v, s2 = v*v;
    #pragma unroll
    for (int o = 16; o; o >>= 1) {
        s1 += __shfl_xor_sync(0xffffffffu, s1, o);
        s2 += __shfl_xor_sync(0xffffffffu, s2, o);
    }
    if (!lane) { red[warp] = s1; red[16+warp] = s2; }
    __syncthreads();
    if (warp == 0) {
        float a = (lane < 16) ? red[lane]    : 0.f;
        float c = (lane < 16) ? red[16+lane] : 0.f;
        #pragma unroll
        for (int o = 8; o; o >>= 1) {
            a += __shfl_xor_sync(0xffffffffu, a, o);
            c += __shfl_xor_sync(0xffffffffu, c, o);
        }
        if (!lane) {
            float m = a * (1.f/512.f);
            red[32] = m;
            red[33] = rsqrtf(c*(1.f/512.f) - m*m + 1e-5f);
        }
    }
    __syncthreads();
    float o = (v - red[32])*red[33]*g[tid] + b[tid];
    Y[base + tid]  = o;
    Yh[base + tid] = __float2half_rn(o);
}

extern "C" void kernel_launch(void* const* d_in, const int* in_sizes, int n_in,
                              void* d_out, int out_size) {
    (void)in_sizes; (void)n_in; (void)out_size;
    const float* vis   = (const float*)d_in[0];
    const float* aud   = (const float*)d_in[1];
    const float* in_W  = (const float*)d_in[2];
    const float* in_b  = (const float*)d_in[3];
    const float* out_W = (const float*)d_in[4];
    const float* out_b = (const float*)d_in[5];

    float* out      = (float*)d_out;
    float* attn_out = out + (size_t)M_ALL*Hd;
    float* cos_out  = attn_out + (size_t)BT*NP*NP;

    float *gx, *gsp, *gz, *gtmp, *gcos;
    __half *gxh, *gsph, *gzh, *gtmph, *gwh;
    cudaGetSymbolAddress((void**)&gx,    g_x);
    cudaGetSymbolAddress((void**)&gsp,   g_sp);
    cudaGetSymbolAddress((void**)&gz,    g_z);
    cudaGetSymbolAddress((void**)&gtmp,  g_tmp);
    cudaGetSymbolAddress((void**)&gcos,  g_cos);
    cudaGetSymbolAddress((void**)&gxh,   g_xh);
    cudaGetSymbolAddress((void**)&gsph,  g_sph);
    cudaGetSymbolAddress((void**)&gzh,   g_zh);
    cudaGetSymbolAddress((void**)&gtmph, g_tmph);
    cudaGetSymbolAddress((void**)&gwh,   g_wh);

    cudaFuncSetAttribute(attn_agg_kernel,
                         cudaFuncAttributeMaxDynamicSharedMemorySize, ATTN_SMEM_BYTES);
    cudaFuncSetAttribute(gemm_fp16,
                         cudaFuncAttributeMaxDynamicSharedMemorySize, GH_SMEM);

    // pre-round the 8 weight matrices to fp16 (RN), one launch
    WPtrs wp;
    wp.p[0] = in_W;  wp.p[1] = out_W;
    wp.p[2] = (const float*)d_in[9];  wp.p[3] = (const float*)d_in[11];
    wp.p[4] = (const float*)d_in[13]; wp.p[5] = (const float*)d_in[17];
    wp.p[6] = (const float*)d_in[19]; wp.p[7] = (const float*)d_in[21];
    round_h_k<<<8192, 256>>>(wp, gwh);
    const __half* W_in  = gwh;
    const __half* W_out = gwh + (size_t)1*512*512;
    const __half* W_l[2][3] = { { gwh+(size_t)2*512*512, gwh+(size_t)3*512*512, gwh+(size_t)4*512*512 },
                                { gwh+(size_t)5*512*512, gwh+(size_t)6*512*512, gwh+(size_t)7*512*512 } };

    // input projection
    concat_kernel<<<(M_ALL*128 + 255)/256, 256>>>(vis, aud, gz, gzh);
    dim3 gAll(4, (M_ALL + 127)/128);
    gemm_fp16<<<gAll, 256, GH_SMEM>>>(gzh, 0, 0, nullptr, 0, W_in, in_b, 0,
                                      nullptr, 0, 0, nullptr, gx, nullptr, 0, 0, M_ALL);

    for (int L = 0; L < 2; L++) {
        const float* edge = (const float*)d_in[6 + L*8];
        const float* lng  = (const float*)d_in[7 + L*8];
        const float* lnb  = (const float*)d_in[8 + L*8];
        const float* bc   = (const float*)d_in[10 + L*8];
        const float* bs   = (const float*)d_in[12 + L*8];

        attn_agg_kernel<<<BT, 512, ATTN_SMEM_BYTES>>>(
            gx, edge, lng, lnb, (L == 1) ? attn_out : nullptr, gsp, gsph);

        cos_kernel<<<(M_T*32 + 255)/256, 256>>>(gsp, gcos, (L == 1) ? cos_out : nullptr);

        dim3 gT(4, (M_T + 127)/128);
        // tc = relu(cos * (prev @ Wc^T) + bc) -> gtmp (dense rows)
        gemm_fp16<<<gT, 256, GH_SMEM>>>(gsph, 1, 0, gcos, 1, W_l[L][0], bc, 1,
                                        nullptr, 0, 0, nullptr, gtmp, nullptr, 0, 0, M_T);
        // z[t+1] = cur + tc + relu((1-cos) * (cur @ Ws^T) + bs)
        gemm_fp16<<<gT, 256, GH_SMEM>>>(gsph, 1, 1, gcos, 2, W_l[L][1], bs, 1,
                                        gsp, 1, 1, gtmp, gz, nullptr, 1, 1, M_T);
        copy_t0<<<(Bsz*NP*128 + 255)/256, 256>>>(gsp, gz);

        ln512<<<M_ALL, 512>>>(gz, lng, lnb, gtmp, gtmph);
        // x = x + relu(LN(z) @ Wo^T)   (also emit half copy of new x)
        gemm_fp16<<<gAll, 256, GH_SMEM>>>(gtmph, 0, 0, nullptr, 0, W_l[L][2], nullptr, 1,
                                          gx, 0, 0, nullptr, gx, gxh, 0, 0, M_ALL);
    }

    // output projection
    gemm_fp16<<<gAll, 256, GH_SMEM>>>(gxh, 0, 0, nullptr, 0, W_out, out_b, 0,
                                      nullptr, 0, 0, nullptr, out, nullptr, 0, 0, M_ALL);
}